// round 2
// baseline (speedup 1.0000x reference)
#include <cuda_runtime.h>
#include <cuda_bf16.h>

#define NEL     20000      // B*NE total electrons
#define T_TICKS 512
#define NXY     48
#define TT      16         // ticks per tile
#define NTILE   32         // 512/16
#define SXC     6          // sensor-x rows per CTA
#define NSXC    8          // 48/6
#define WCUT    14         // temporal truncation half-window
#define NB      128        // z buckets (width 4 ticks)
#define CHUNK   64         // electrons staged per SMEM pass
#define BLK_D   288        // 6*48 threads

// ---- scratch (__device__ globals; no allocation allowed) ----
__device__ float g_gx [NEL * 48];   // raw gaussian in x, per electron (sorted order)
__device__ float g_cgy[NEL * 48];   // c * gaussian in y, per electron (sorted order)
__device__ float g_z  [NEL];        // z position (sorted order)
__device__ int   g_hist[NB];
__device__ int   g_off [NB + 1];
__device__ int   g_cursor[NB];

// ------------------------------------------------------------------
__global__ void k_zero() {
    if (threadIdx.x < NB) g_hist[threadIdx.x] = 0;
}

__global__ void k_hist(const float* __restrict__ zp) {
    int i = blockIdx.x * blockDim.x + threadIdx.x;
    if (i < NEL) {
        int b = (int)zp[i] >> 2;
        b = min(max(b, 0), NB - 1);
        atomicAdd(&g_hist[b], 1);
    }
}

__global__ void k_scan() {
    int s = 0;
    for (int i = 0; i < NB; i++) {
        g_off[i] = s;
        g_cursor[i] = s;
        s += g_hist[i];
    }
    g_off[NB] = s;
}

// ------------------------------------------------------------------
// Per-electron precompute: MLP (2->64->128->1), fold mask + all norm
// constants into c, emit raw gx[48], c*gy[48], z, scattered into
// z-bucket-sorted order.
__global__ void k_pre(const float* __restrict__ si, const float* __restrict__ zp,
                      const float* __restrict__ mk,
                      const float* __restrict__ W1, const float* __restrict__ b1,
                      const float* __restrict__ W2, const float* __restrict__ b2,
                      const float* __restrict__ W3, const float* __restrict__ b3,
                      const float* __restrict__ el, const float* __restrict__ sloc)
{
    __shared__ float W1s[128], b1s[64], W2s[64 * 128], b2s[128], W3s[128];
    __shared__ float axs[48], ays[48];
    int tid = threadIdx.x;
    if (tid < 128) W1s[tid] = W1[tid];
    if (tid < 64)  b1s[tid] = b1[tid];
    for (int i = tid; i < 64 * 128; i += blockDim.x) W2s[i] = W2[i];
    if (tid < 128) { b2s[tid] = b2[tid]; W3s[tid] = W3[tid]; }
    if (tid < 48)  { axs[tid] = sloc[tid * 96]; ays[tid] = sloc[tid * 2 + 1]; }
    __syncthreads();

    int i = blockIdx.x * blockDim.x + tid;
    if (i >= NEL) return;

    float x = si[2 * i], y = si[2 * i + 1];

    float h2[128];
#pragma unroll
    for (int j = 0; j < 128; j++) h2[j] = b2s[j];
    for (int k = 0; k < 64; k++) {
        float h1k = fmaf(x, W1s[k], fmaf(y, W1s[64 + k], b1s[k]));
        h1k = fmaxf(h1k, 0.0f);
#pragma unroll
        for (int j = 0; j < 128; j++) h2[j] = fmaf(h1k, W2s[k * 128 + j], h2[j]);
    }
    float resp = b3[0];
#pragma unroll
    for (int j = 0; j < 128; j++) resp = fmaf(fmaxf(h2[j], 0.0f), W3s[j], resp);

    float es = el[0];
    // c = response * mask * 100/(es*EL_NORM) * GAUSS_NORM/sqrt(BIN_SIGMA)
    float c = resp * mk[i] * (100.0f / (es * 2.5066f)) * 0.17841241161f;

    float z = zp[i];
    int b = min(max((int)z >> 2, 0), NB - 1);
    int pos = atomicAdd(&g_cursor[b], 1);

    float inv = -0.5f / (es * es);
    float4* pgx = (float4*)(g_gx  + (size_t)pos * 48);
    float4* pgy = (float4*)(g_cgy + (size_t)pos * 48);
#pragma unroll
    for (int q = 0; q < 12; q++) {
        float d0 = x - axs[4 * q + 0], d1 = x - axs[4 * q + 1];
        float d2 = x - axs[4 * q + 2], d3 = x - axs[4 * q + 3];
        pgx[q] = make_float4(__expf(d0 * d0 * inv), __expf(d1 * d1 * inv),
                             __expf(d2 * d2 * inv), __expf(d3 * d3 * inv));
    }
#pragma unroll
    for (int q = 0; q < 12; q++) {
        float d0 = y - ays[4 * q + 0], d1 = y - ays[4 * q + 1];
        float d2 = y - ays[4 * q + 2], d3 = y - ays[4 * q + 3];
        pgy[q] = make_float4(c * __expf(d0 * d0 * inv), c * __expf(d1 * d1 * inv),
                             c * __expf(d2 * d2 * inv), c * __expf(d3 * d3 * inv));
    }
    g_z[pos] = z;
}

// ------------------------------------------------------------------
// Main accumulation. One CTA = (t-tile of 16 ticks) x (6 sx rows).
// Each thread owns one (sx, sy), acc[16] in registers.
__global__ __launch_bounds__(BLK_D) void k_main(float* __restrict__ out)
{
    __shared__ float s_gx[CHUNK * SXC];
    __shared__ float s_gy[CHUNK * 48];
    __shared__ float s_ev[CHUNK * TT];

    int tid = threadIdx.x;
    int t0  = blockIdx.x * TT;
    int sx0 = blockIdx.y * SXC;
    int sxl = tid / 48;
    int sy  = tid - sxl * 48;

    int blo = max(t0 - WCUT, 0) >> 2;
    int bhi = min(t0 + TT - 1 + WCUT, T_TICKS - 1) >> 2;
    int eb = g_off[blo], ee = g_off[bhi + 1];

    float acc[TT];
#pragma unroll
    for (int k = 0; k < TT; k++) acc[k] = 0.0f;

    for (int e0 = eb; e0 < ee; e0 += CHUNK) {
        int cnt = min(CHUNK, ee - e0);
        __syncthreads();
        // stage gx slice (only the 6 rows this CTA needs)
        for (int idx = tid; idx < CHUNK * SXC; idx += BLK_D) {
            int e = idx / SXC;
            int j = idx - e * SXC;
            s_gx[idx] = (e < cnt) ? g_gx[(size_t)(e0 + e) * 48 + sx0 + j] : 0.0f;
        }
        // stage full c*gy rows (vectorized; contiguous in sorted layout)
        {
            const float4* src = (const float4*)(g_cgy + (size_t)e0 * 48);
            float4* dst = (float4*)s_gy;
            int n4 = cnt * 12;
            for (int idx = tid; idx < CHUNK * 12; idx += BLK_D)
                dst[idx] = (idx < n4) ? src[idx] : make_float4(0.f, 0.f, 0.f, 0.f);
        }
        // compute time-gaussian weights for this tile
        for (int idx = tid; idx < CHUNK * TT; idx += BLK_D) {
            int e = idx >> 4;
            int k = idx & (TT - 1);
            float z = (e < cnt) ? g_z[e0 + e] : 1.0e9f;
            float d = (float)(t0 + k) - z;
            s_ev[idx] = __expf(-0.1f * d * d);
        }
        __syncthreads();

        const float4* evp = (const float4*)s_ev;
#pragma unroll 2
        for (int e = 0; e < CHUNK; e++) {
            float gxv = s_gx[e * SXC + sxl];
            // spatial-sparsity skip: warp-uniform (gx is broadcast per warp)
            if (!__any_sync(0xffffffffu, gxv > 1e-10f)) continue;
            float v = gxv * s_gy[e * 48 + sy];
            float4 a = evp[e * 4 + 0];
            float4 b = evp[e * 4 + 1];
            float4 c = evp[e * 4 + 2];
            float4 d = evp[e * 4 + 3];
            acc[0]  = fmaf(v, a.x, acc[0]);  acc[1]  = fmaf(v, a.y, acc[1]);
            acc[2]  = fmaf(v, a.z, acc[2]);  acc[3]  = fmaf(v, a.w, acc[3]);
            acc[4]  = fmaf(v, b.x, acc[4]);  acc[5]  = fmaf(v, b.y, acc[5]);
            acc[6]  = fmaf(v, b.z, acc[6]);  acc[7]  = fmaf(v, b.w, acc[7]);
            acc[8]  = fmaf(v, c.x, acc[8]);  acc[9]  = fmaf(v, c.y, acc[9]);
            acc[10] = fmaf(v, c.z, acc[10]); acc[11] = fmaf(v, c.w, acc[11]);
            acc[12] = fmaf(v, d.x, acc[12]); acc[13] = fmaf(v, d.y, acc[13]);
            acc[14] = fmaf(v, d.z, acc[14]); acc[15] = fmaf(v, d.w, acc[15]);
        }
    }

    int sx = sx0 + sxl;
    float4* o4 = (float4*)(out + ((size_t)(sx * NXY + sy)) * T_TICKS + t0);
    o4[0] = make_float4(acc[0],  acc[1],  acc[2],  acc[3]);
    o4[1] = make_float4(acc[4],  acc[5],  acc[6],  acc[7]);
    o4[2] = make_float4(acc[8],  acc[9],  acc[10], acc[11]);
    o4[3] = make_float4(acc[12], acc[13], acc[14], acc[15]);
}

// ------------------------------------------------------------------
extern "C" void kernel_launch(void* const* d_in, const int* in_sizes, int n_in,
                              void* d_out, int out_size)
{
    const float* si = (const float*)d_in[0];   // simulator_input (4,5000,2)
    const float* zp = (const float*)d_in[1];   // z_positions (4,5000)
    const float* mk = (const float*)d_in[2];   // mask (4,5000)
    const float* W1 = (const float*)d_in[3];
    const float* b1 = (const float*)d_in[4];
    const float* W2 = (const float*)d_in[5];
    const float* b2 = (const float*)d_in[6];
    const float* W3 = (const float*)d_in[7];
    const float* b3 = (const float*)d_in[8];
    const float* el = (const float*)d_in[9];
    const float* sl = (const float*)d_in[10];  // sensor_locations (48,48,2)
    float* out = (float*)d_out;                // (48,48,512)

    k_zero<<<1, 128>>>();
    k_hist<<<(NEL + 255) / 256, 256>>>(zp);
    k_scan<<<1, 1>>>();
    k_pre <<<(NEL + 127) / 128, 128>>>(si, zp, mk, W1, b1, W2, b2, W3, b3, el, sl);
    k_main<<<dim3(NTILE, NSXC), BLK_D>>>(out);
}

// round 4
// speedup vs baseline: 1.5051x; 1.5051x over previous
#include <cuda_runtime.h>
#include <cuda_bf16.h>

#define NEL     20000      // B*NE total electrons
#define T_TICKS 512
#define NXY     48
#define TT      16         // ticks per tile
#define NTILE   32         // 512/16
#define SXC     6          // sensor-x rows per CTA
#define NSXC    8          // 48/6
#define WCUT    9          // temporal truncation half-window (exp(-0.1*100)=4.5e-5)
#define NB      128        // z buckets (width 4 ticks)
#define CHUNK   64         // electrons staged per SMEM pass
#define BLK_D   288        // 6*48 threads

// ---- scratch (__device__ globals; no allocation allowed) ----
__device__ float g_gx [NEL * 48];   // raw gaussian in x, per electron (sorted order)
__device__ float g_cgy[NEL * 48];   // c * gaussian in y, per electron (sorted order)
__device__ float g_z  [NEL];        // z position (sorted order)
__device__ float g_ex [NEL];        // x coordinate (sorted order) for relevance test
__device__ int   g_hist[NB];
__device__ int   g_off [NB + 1];
__device__ int   g_cursor[NB];

// ------------------------------------------------------------------
__global__ void k_zero() {
    if (threadIdx.x < NB) g_hist[threadIdx.x] = 0;
}

__global__ void k_hist(const float* __restrict__ zp) {
    int i = blockIdx.x * blockDim.x + threadIdx.x;
    if (i < NEL) {
        int b = (int)zp[i] >> 2;
        b = min(max(b, 0), NB - 1);
        atomicAdd(&g_hist[b], 1);
    }
}

__global__ void k_scan() {
    int s = 0;
    for (int i = 0; i < NB; i++) {
        g_off[i] = s;
        g_cursor[i] = s;
        s += g_hist[i];
    }
    g_off[NB] = s;
}

// ------------------------------------------------------------------
// Per-electron precompute, 2 threads per electron (each owns 64 of h2).
// MLP (2->64->128->1), fold mask + norm constants into c, emit raw gx[48],
// c*gy[48], z, x, scattered into z-bucket-sorted order.
__global__ __launch_bounds__(256) void k_pre(
                      const float* __restrict__ si, const float* __restrict__ zp,
                      const float* __restrict__ mk,
                      const float* __restrict__ W1, const float* __restrict__ b1,
                      const float* __restrict__ W2, const float* __restrict__ b2,
                      const float* __restrict__ W3, const float* __restrict__ b3,
                      const float* __restrict__ el, const float* __restrict__ sloc)
{
    __shared__ float  W1s[128], b1s[64];
    __shared__ float4 W2s4[64 * 32];   // [k][32 float4] = [64][128 floats]
    __shared__ float4 b2s4[32], W3s4[32];
    __shared__ float  axs[48], ays[48];
    int tid = threadIdx.x;
    if (tid < 128) W1s[tid] = W1[tid];
    if (tid < 64)  b1s[tid] = b1[tid];
    {
        const float4* w2 = (const float4*)W2;
        for (int i = tid; i < 64 * 32; i += blockDim.x) W2s4[i] = w2[i];
    }
    if (tid < 32) { b2s4[tid] = ((const float4*)b2)[tid]; W3s4[tid] = ((const float4*)W3)[tid]; }
    if (tid < 48) { axs[tid] = sloc[tid * 96]; ays[tid] = sloc[tid * 2 + 1]; }
    __syncthreads();

    int eidx = blockIdx.x * 128 + (tid >> 1);
    int half = tid & 1;
    bool valid = eidx < NEL;
    int e = valid ? eidx : NEL - 1;

    float x = si[2 * e], y = si[2 * e + 1];

    float4 h2[16];
#pragma unroll
    for (int q = 0; q < 16; q++) h2[q] = b2s4[half * 16 + q];

    for (int k = 0; k < 64; k++) {
        float h1k = fmaf(x, W1s[k], fmaf(y, W1s[64 + k], b1s[k]));
        h1k = fmaxf(h1k, 0.0f);
        const float4* wp = &W2s4[k * 32 + half * 16];
#pragma unroll
        for (int q = 0; q < 16; q++) {
            float4 w = wp[q];
            h2[q].x = fmaf(h1k, w.x, h2[q].x);
            h2[q].y = fmaf(h1k, w.y, h2[q].y);
            h2[q].z = fmaf(h1k, w.z, h2[q].z);
            h2[q].w = fmaf(h1k, w.w, h2[q].w);
        }
    }
    float rp = 0.0f;
#pragma unroll
    for (int q = 0; q < 16; q++) {
        float4 w = W3s4[half * 16 + q];
        rp = fmaf(fmaxf(h2[q].x, 0.0f), w.x, rp);
        rp = fmaf(fmaxf(h2[q].y, 0.0f), w.y, rp);
        rp = fmaf(fmaxf(h2[q].z, 0.0f), w.z, rp);
        rp = fmaf(fmaxf(h2[q].w, 0.0f), w.w, rp);
    }
    float resp = rp + __shfl_xor_sync(0xffffffffu, rp, 1) + b3[0];

    float es = el[0];
    float c = resp * mk[e] * (100.0f / (es * 2.5066f)) * 0.17841241161f;
    float z = zp[e];

    int pos = 0;
    if (valid && half == 0) {
        int b = min(max((int)z >> 2, 0), NB - 1);
        pos = atomicAdd(&g_cursor[b], 1);
    }
    pos = __shfl_sync(0xffffffffu, pos, (tid & 31) & ~1);
    if (!valid) return;

    float inv = -0.5f / (es * es);
    if (half == 0) {
        float4* pgx = (float4*)(g_gx + (size_t)pos * 48);
#pragma unroll
        for (int q = 0; q < 12; q++) {
            float d0 = x - axs[4 * q + 0], d1 = x - axs[4 * q + 1];
            float d2 = x - axs[4 * q + 2], d3 = x - axs[4 * q + 3];
            pgx[q] = make_float4(__expf(d0 * d0 * inv), __expf(d1 * d1 * inv),
                                 __expf(d2 * d2 * inv), __expf(d3 * d3 * inv));
        }
        g_z[pos]  = z;
        g_ex[pos] = x;
    } else {
        float4* pgy = (float4*)(g_cgy + (size_t)pos * 48);
#pragma unroll
        for (int q = 0; q < 12; q++) {
            float d0 = y - ays[4 * q + 0], d1 = y - ays[4 * q + 1];
            float d2 = y - ays[4 * q + 2], d3 = y - ays[4 * q + 3];
            pgy[q] = make_float4(c * __expf(d0 * d0 * inv), c * __expf(d1 * d1 * inv),
                                 c * __expf(d2 * d2 * inv), c * __expf(d3 * d3 * inv));
        }
    }
}

// ------------------------------------------------------------------
// Main accumulation. One CTA = (t-tile of 16 ticks) x (6 sx rows).
// Per chunk: compact the z-window electrons down to the ones spatially
// relevant to this strip (ballot+prefix), stage only survivors, then a
// branch-free inner loop: each thread owns one (sx,sy), acc[16] in regs.
__global__ __launch_bounds__(BLK_D) void k_main(float* __restrict__ out,
                                                const float* __restrict__ el,
                                                const float* __restrict__ sloc)
{
    __shared__ float s_gx[CHUNK * SXC];
    __shared__ float s_gy[CHUNK * 48];
    __shared__ float s_ev[CHUNK * TT];
    __shared__ int   s_idx[CHUNK];
    __shared__ int   s_cnt;

    int tid = threadIdx.x;
    int t0  = blockIdx.x * TT;
    int sx0 = blockIdx.y * SXC;
    int sxl = tid / 48;
    int sy  = tid - sxl * 48;

    float es  = el[0];
    float thr = 4.57f * es;                    // gx < 3e-5 beyond this distance
    float xlo = sloc[sx0 * 96];
    float xhi = sloc[(sx0 + SXC - 1) * 96];

    int blo = max(t0 - WCUT, 0) >> 2;
    int bhi = min(t0 + TT - 1 + WCUT, T_TICKS - 1) >> 2;
    int eb = g_off[blo], ee = g_off[bhi + 1];

    float acc[TT];
#pragma unroll
    for (int k = 0; k < TT; k++) acc[k] = 0.0f;

    for (int e0 = eb; e0 < ee; e0 += CHUNK) {
        int cnt = min(CHUNK, ee - e0);
        __syncthreads();               // prev inner loop done before smem reuse
        if (tid == 0) s_cnt = 0;
        __syncthreads();

        // --- compaction: warps 0,1 test relevance of 64 electrons ---
        if (tid < CHUNK) {
            bool rel = false;
            int e = e0 + tid;
            if (tid < cnt) {
                float x = g_ex[e];
                float d = fmaxf(fmaxf(xlo - x, x - xhi), 0.0f);
                rel = d < thr;
            }
            unsigned m = __ballot_sync(0xffffffffu, rel);
            int base = 0;
            if ((tid & 31) == 0) base = atomicAdd(&s_cnt, __popc(m));
            base = __shfl_sync(0xffffffffu, base, 0);
            if (rel) s_idx[base + __popc(m & ((1u << (tid & 31)) - 1u))] = e;
        }
        __syncthreads();
        int mm = s_cnt;
        if (mm == 0) continue;

        // --- stage survivors ---
        for (int idx = tid; idx < mm * SXC; idx += BLK_D) {
            int e = idx / SXC;
            int j = idx - e * SXC;
            s_gx[idx] = g_gx[(size_t)s_idx[e] * 48 + sx0 + j];
        }
        {
            float4* dst = (float4*)s_gy;
            for (int idx = tid; idx < mm * 12; idx += BLK_D) {
                int e = idx / 12;
                int j = idx - e * 12;
                dst[idx] = ((const float4*)(g_cgy + (size_t)s_idx[e] * 48))[j];
            }
        }
        for (int idx = tid; idx < mm * TT; idx += BLK_D) {
            int e = idx >> 4;
            int k = idx & (TT - 1);
            float z = g_z[s_idx[e]];
            float d = (float)(t0 + k) - z;
            s_ev[idx] = __expf(-0.1f * d * d);
        }
        __syncthreads();

        // --- branch-free accumulate over survivors ---
        const float4* evp = (const float4*)s_ev;
#pragma unroll 2
        for (int e = 0; e < mm; e++) {
            float v = s_gx[e * SXC + sxl] * s_gy[e * 48 + sy];
            float4 a = evp[e * 4 + 0];
            float4 b = evp[e * 4 + 1];
            float4 c = evp[e * 4 + 2];
            float4 d = evp[e * 4 + 3];
            acc[0]  = fmaf(v, a.x, acc[0]);  acc[1]  = fmaf(v, a.y, acc[1]);
            acc[2]  = fmaf(v, a.z, acc[2]);  acc[3]  = fmaf(v, a.w, acc[3]);
            acc[4]  = fmaf(v, b.x, acc[4]);  acc[5]  = fmaf(v, b.y, acc[5]);
            acc[6]  = fmaf(v, b.z, acc[6]);  acc[7]  = fmaf(v, b.w, acc[7]);
            acc[8]  = fmaf(v, c.x, acc[8]);  acc[9]  = fmaf(v, c.y, acc[9]);
            acc[10] = fmaf(v, c.z, acc[10]); acc[11] = fmaf(v, c.w, acc[11]);
            acc[12] = fmaf(v, d.x, acc[12]); acc[13] = fmaf(v, d.y, acc[13]);
            acc[14] = fmaf(v, d.z, acc[14]); acc[15] = fmaf(v, d.w, acc[15]);
        }
    }

    int sx = sx0 + sxl;
    float4* o4 = (float4*)(out + ((size_t)(sx * NXY + sy)) * T_TICKS + t0);
    o4[0] = make_float4(acc[0],  acc[1],  acc[2],  acc[3]);
    o4[1] = make_float4(acc[4],  acc[5],  acc[6],  acc[7]);
    o4[2] = make_float4(acc[8],  acc[9],  acc[10], acc[11]);
    o4[3] = make_float4(acc[12], acc[13], acc[14], acc[15]);
}

// ------------------------------------------------------------------
extern "C" void kernel_launch(void* const* d_in, const int* in_sizes, int n_in,
                              void* d_out, int out_size)
{
    const float* si = (const float*)d_in[0];   // simulator_input (4,5000,2)
    const float* zp = (const float*)d_in[1];   // z_positions (4,5000)
    const float* mk = (const float*)d_in[2];   // mask (4,5000)
    const float* W1 = (const float*)d_in[3];
    const float* b1 = (const float*)d_in[4];
    const float* W2 = (const float*)d_in[5];
    const float* b2 = (const float*)d_in[6];
    const float* W3 = (const float*)d_in[7];
    const float* b3 = (const float*)d_in[8];
    const float* el = (const float*)d_in[9];
    const float* sl = (const float*)d_in[10];  // sensor_locations (48,48,2)
    float* out = (float*)d_out;                // (48,48,512)

    k_zero<<<1, 128>>>();
    k_hist<<<(NEL + 255) / 256, 256>>>(zp);
    k_scan<<<1, 1>>>();
    k_pre <<<(NEL + 127) / 128, 256>>>(si, zp, mk, W1, b1, W2, b2, W3, b3, el, sl);
    k_main<<<dim3(NTILE, NSXC), BLK_D>>>(out, el, sl);
}

// round 5
// speedup vs baseline: 1.8176x; 1.2077x over previous
#include <cuda_runtime.h>
#include <cuda_bf16.h>

#define NEL     20000      // B*NE total electrons
#define T_TICKS 512
#define NXY     48
#define TT      16         // ticks per tile
#define NTILE   32         // 512/16
#define SXC     6          // sensor-x rows per strip
#define NSTRIP  8          // 48/6
#define WCUT    9          // temporal truncation half-window
#define NB      128        // z buckets (width 4 ticks)
#define CHUNK   64         // electrons per SMEM pass
#define BLK_D   288        // 6*48 threads
#define NSB     (NSTRIP*NB)   // 1024 (strip,bucket) cells
#define MAXENT  (NEL*8)       // worst-case CSR entries

// ---- scratch (__device__ globals; no allocation allowed) ----
__device__ float g_gx [NEL * 48];    // raw gaussian in x (sorted order)
__device__ float g_cgy[NEL * 48];    // c * gaussian in y (sorted order)
__device__ float g_z  [NEL];         // z (sorted order)
__device__ float g_ex [NEL];         // x (sorted order)
__device__ int   g_hist[NB];
__device__ int   g_off [NB + 1];
__device__ int   g_cursor[NB];
__device__ int   g_scount[NSB];      // per (strip,bucket) entry counts
__device__ int   g_soff  [NSB + 1];  // CSR offsets
__device__ int   g_scur  [NSB];      // scatter cursors
__device__ int   g_sidx[MAXENT];     // entry -> sorted electron pos
__device__ float g_sz  [MAXENT];     // entry z
__device__ float g_sgx [MAXENT * SXC]; // entry gx slice for its strip (coalesced)
__device__ float g_part[NXY * NXY * T_TICKS]; // split-1 partial output

// ---- packed f32x2 helpers ----
__device__ __forceinline__ unsigned long long pack2(float v) {
    unsigned long long r;
    unsigned u = __float_as_uint(v);
    asm("mov.b64 %0, {%1, %1};" : "=l"(r) : "r"(u));
    return r;
}
__device__ __forceinline__ void fma2(unsigned long long& acc,
                                     unsigned long long a, unsigned long long b) {
    asm("fma.rn.f32x2 %0, %1, %2, %0;" : "+l"(acc) : "l"(a), "l"(b));
}
__device__ __forceinline__ void unpack2(unsigned long long p, float& lo, float& hi) {
    unsigned a, b;
    asm("mov.b64 {%0, %1}, %2;" : "=r"(a), "=r"(b) : "l"(p));
    lo = __uint_as_float(a); hi = __uint_as_float(b);
}

// ------------------------------------------------------------------
__global__ void k_zero() {
    int t = threadIdx.x;
    g_scount[t] = 0;
    if (t < NB) g_hist[t] = 0;
}

// bucket histogram + per-(strip,bucket) counts
__global__ void k_hist(const float* __restrict__ zp, const float* __restrict__ si,
                       const float* __restrict__ el, const float* __restrict__ sloc) {
    __shared__ float sxlo[NSTRIP], sxhi[NSTRIP];
    if (threadIdx.x < NSTRIP) {
        sxlo[threadIdx.x] = sloc[(threadIdx.x * SXC) * 96];
        sxhi[threadIdx.x] = sloc[(threadIdx.x * SXC + SXC - 1) * 96];
    }
    __syncthreads();
    int i = blockIdx.x * blockDim.x + threadIdx.x;
    if (i >= NEL) return;
    int b = min(max((int)zp[i] >> 2, 0), NB - 1);
    atomicAdd(&g_hist[b], 1);
    float x = si[2 * i];
    float thr = 4.57f * el[0];
#pragma unroll
    for (int s = 0; s < NSTRIP; s++) {
        float d = fmaxf(fmaxf(sxlo[s] - x, x - sxhi[s]), 0.0f);
        if (d < thr) atomicAdd(&g_scount[s * NB + b], 1);
    }
}

// exclusive scans: 1024-cell strip CSR + 128-bucket z offsets (one block, 1024 thr)
__global__ void k_scan() {
    __shared__ int sd[NSB];
    int tid = threadIdx.x;
    int v = g_scount[tid];
    sd[tid] = v; __syncthreads();
    for (int d = 1; d < NSB; d <<= 1) {
        int add = (tid >= d) ? sd[tid - d] : 0;
        __syncthreads();
        sd[tid] += add;
        __syncthreads();
    }
    int inc = sd[tid];
    g_soff[tid] = inc - v;
    g_scur[tid] = inc - v;
    if (tid == NSB - 1) g_soff[NSB] = inc;
    __syncthreads();
    int v2 = (tid < NB) ? g_hist[tid] : 0;
    if (tid < NB) sd[tid] = v2;
    __syncthreads();
    for (int d = 1; d < NB; d <<= 1) {
        int add = (tid >= d && tid < NB) ? sd[tid - d] : 0;
        __syncthreads();
        if (tid < NB) sd[tid] += add;
        __syncthreads();
    }
    if (tid < NB) {
        int i2 = sd[tid];
        g_off[tid] = i2 - v2;
        g_cursor[tid] = i2 - v2;
        if (tid == NB - 1) g_off[NB] = i2;
    }
}

// ------------------------------------------------------------------
// Per-electron precompute. 8 threads cooperate on 4 electrons:
// octant o = tid&7 owns h2 dims [o*16, o*16+16); each loaded W2 float4
// is reused across 4 electrons (4x less SMEM traffic than before).
__global__ __launch_bounds__(256) void k_pre(
                      const float* __restrict__ si, const float* __restrict__ zp,
                      const float* __restrict__ mk,
                      const float* __restrict__ W1, const float* __restrict__ b1,
                      const float* __restrict__ W2, const float* __restrict__ b2,
                      const float* __restrict__ W3, const float* __restrict__ b3,
                      const float* __restrict__ el, const float* __restrict__ sloc)
{
    __shared__ float  W1s[128], b1s[64];
    __shared__ float4 W2s4[64 * 32];
    __shared__ float4 b2s4[32], W3s4[32];
    __shared__ float  axs[48], ays[48];
    int tid = threadIdx.x;
    if (tid < 128) W1s[tid] = W1[tid];
    if (tid < 64)  b1s[tid] = b1[tid];
    {
        const float4* w2 = (const float4*)W2;
        for (int i = tid; i < 64 * 32; i += blockDim.x) W2s4[i] = w2[i];
    }
    if (tid < 32) { b2s4[tid] = ((const float4*)b2)[tid]; W3s4[tid] = ((const float4*)W3)[tid]; }
    if (tid < 48) { axs[tid] = sloc[tid * 96]; ays[tid] = sloc[tid * 2 + 1]; }
    __syncthreads();

    int lane = tid & 31;
    int o    = tid & 7;                       // octant
    int grp  = tid >> 3;                      // 32 groups per CTA
    int gbase = (blockIdx.x * 32 + grp) * 4;  // 4 electrons per group
    if (gbase >= NEL) return;                 // exits whole warps (see layout)

    float xs[4], ys[4];
#pragma unroll
    for (int i = 0; i < 4; i++) { xs[i] = si[2 * (gbase + i)]; ys[i] = si[2 * (gbase + i) + 1]; }

    float4 h2[4][4];
#pragma unroll
    for (int e = 0; e < 4; e++)
#pragma unroll
        for (int q = 0; q < 4; q++) h2[e][q] = b2s4[o * 4 + q];

    for (int k = 0; k < 64; k++) {
        float w1a = W1s[k], w1b = W1s[64 + k], bb = b1s[k];
        float h1[4];
#pragma unroll
        for (int e = 0; e < 4; e++)
            h1[e] = fmaxf(fmaf(xs[e], w1a, fmaf(ys[e], w1b, bb)), 0.0f);
        const float4* wp = &W2s4[k * 32 + o * 4];
#pragma unroll
        for (int q = 0; q < 4; q++) {
            float4 w = wp[q];
#pragma unroll
            for (int e = 0; e < 4; e++) {
                h2[e][q].x = fmaf(h1[e], w.x, h2[e][q].x);
                h2[e][q].y = fmaf(h1[e], w.y, h2[e][q].y);
                h2[e][q].z = fmaf(h1[e], w.z, h2[e][q].z);
                h2[e][q].w = fmaf(h1[e], w.w, h2[e][q].w);
            }
        }
    }

    float rp[4] = {0.f, 0.f, 0.f, 0.f};
#pragma unroll
    for (int q = 0; q < 4; q++) {
        float4 w = W3s4[o * 4 + q];
#pragma unroll
        for (int e = 0; e < 4; e++) {
            rp[e] = fmaf(fmaxf(h2[e][q].x, 0.f), w.x, rp[e]);
            rp[e] = fmaf(fmaxf(h2[e][q].y, 0.f), w.y, rp[e]);
            rp[e] = fmaf(fmaxf(h2[e][q].z, 0.f), w.z, rp[e]);
            rp[e] = fmaf(fmaxf(h2[e][q].w, 0.f), w.w, rp[e]);
        }
    }
#pragma unroll
    for (int d = 1; d < 8; d <<= 1)
#pragma unroll
        for (int e = 0; e < 4; e++)
            rp[e] += __shfl_xor_sync(0xffffffffu, rp[e], d);

    float es = el[0];
    float inv = -0.5f / (es * es);
    float cnorm = (100.0f / (es * 2.5066f)) * 0.17841241161f;

    // lanes o=2m,2m+1 handle output for electron m (gx / gy roles)
    int myE = o >> 1;
    int ei  = gbase + myE;
    float resp = rp[myE] + b3[0];
    float c = resp * mk[ei] * cnorm;
    float z = zp[ei];
    float x = xs[myE], y = ys[myE];

    int posv = 0;
    if ((o & 1) == 0) {
        int b = min(max((int)z >> 2, 0), NB - 1);
        posv = atomicAdd(&g_cursor[b], 1);
    }
    int pos = __shfl_sync(0xffffffffu, posv, lane & ~1);

    if ((o & 1) == 0) {
        float4* pgx = (float4*)(g_gx + (size_t)pos * 48);
#pragma unroll
        for (int q = 0; q < 12; q++) {
            float d0 = x - axs[4 * q + 0], d1 = x - axs[4 * q + 1];
            float d2 = x - axs[4 * q + 2], d3 = x - axs[4 * q + 3];
            pgx[q] = make_float4(__expf(d0 * d0 * inv), __expf(d1 * d1 * inv),
                                 __expf(d2 * d2 * inv), __expf(d3 * d3 * inv));
        }
        g_z[pos]  = z;
        g_ex[pos] = x;
    } else {
        float4* pgy = (float4*)(g_cgy + (size_t)pos * 48);
#pragma unroll
        for (int q = 0; q < 12; q++) {
            float d0 = y - ays[4 * q + 0], d1 = y - ays[4 * q + 1];
            float d2 = y - ays[4 * q + 2], d3 = y - ays[4 * q + 3];
            pgy[q] = make_float4(c * __expf(d0 * d0 * inv), c * __expf(d1 * d1 * inv),
                                 c * __expf(d2 * d2 * inv), c * __expf(d3 * d3 * inv));
        }
    }
}

// ------------------------------------------------------------------
// Build per-(strip,bucket) CSR entry lists: index, z, and the 6-float gx
// slice for that strip (pre-gathered for coalesced staging in k_main).
__global__ void k_scatter(const float* __restrict__ el, const float* __restrict__ sloc) {
    __shared__ float sxlo[NSTRIP], sxhi[NSTRIP];
    if (threadIdx.x < NSTRIP) {
        sxlo[threadIdx.x] = sloc[(threadIdx.x * SXC) * 96];
        sxhi[threadIdx.x] = sloc[(threadIdx.x * SXC + SXC - 1) * 96];
    }
    __syncthreads();
    int pos = blockIdx.x * blockDim.x + threadIdx.x;
    if (pos >= NEL) return;
    float x = g_ex[pos], z = g_z[pos];
    int b = min(max((int)z >> 2, 0), NB - 1);
    float thr = 4.57f * el[0];
#pragma unroll
    for (int s = 0; s < NSTRIP; s++) {
        float d = fmaxf(fmaxf(sxlo[s] - x, x - sxhi[s]), 0.0f);
        if (d < thr) {
            int q = atomicAdd(&g_scur[s * NB + b], 1);
            g_sidx[q] = pos;
            g_sz[q]   = z;
#pragma unroll
            for (int j = 0; j < SXC; j++)
                g_sgx[q * SXC + j] = g_gx[(size_t)pos * 48 + s * SXC + j];
        }
    }
}

// ------------------------------------------------------------------
// Main accumulation. CTA = (t-tile, strip, split). Dense CSR chunks,
// packed-f32x2 inner loop, acc as 8 fp32 pairs per thread.
__global__ __launch_bounds__(BLK_D) void k_main(float* __restrict__ out)
{
    __shared__ float      s_gx[CHUNK * SXC];
    __shared__ float4     s_gy4[CHUNK * 12];
    __shared__ ulonglong2 s_ev2[CHUNK * 4];
    float* s_ev = (float*)s_ev2;
    float* s_gy = (float*)s_gy4;

    int tid = threadIdx.x;
    int t0  = blockIdx.x * TT;
    int s   = blockIdx.y;
    int sxl = tid / 48;
    int sy  = tid - sxl * 48;

    int blo = max(t0 - WCUT, 0) >> 2;
    int bhi = min(t0 + TT - 1 + WCUT, T_TICKS - 1) >> 2;
    int rb = g_soff[s * NB + blo], re = g_soff[s * NB + bhi + 1];
    int len = re - rb;
    int half = (len + 1) >> 1;
    int cb = rb + blockIdx.z * half;
    int ce = min(cb + half, re);

    unsigned long long acc2[8];
#pragma unroll
    for (int j = 0; j < 8; j++) acc2[j] = 0ull;

    for (int c0 = cb; c0 < ce; c0 += CHUNK) {
        int cnt = min(CHUNK, ce - c0);
        __syncthreads();                       // previous inner pass done
        // stage gx slices (coalesced from per-strip layout)
        for (int idx = tid; idx < cnt * SXC; idx += BLK_D)
            s_gx[idx] = g_sgx[(size_t)c0 * SXC + idx];
        // stage c*gy rows (gather via entry index; 192B segments)
        for (int idx = tid; idx < cnt * 12; idx += BLK_D) {
            int e = idx / 12;
            int j = idx - e * 12;
            s_gy4[idx] = ((const float4*)(g_cgy + (size_t)g_sidx[c0 + e] * 48))[j];
        }
        // time-gaussian weights for this tile
        for (int idx = tid; idx < cnt * TT; idx += BLK_D) {
            int e = idx >> 4;
            int k = idx & (TT - 1);
            float d = (float)(t0 + k) - g_sz[c0 + e];
            s_ev[idx] = __expf(-0.1f * d * d);
        }
        __syncthreads();

#pragma unroll 2
        for (int e = 0; e < cnt; e++) {
            float v = s_gx[e * SXC + sxl] * s_gy[e * 48 + sy];
            unsigned long long v2 = pack2(v);
            const ulonglong2* ep = &s_ev2[e * 4];
#pragma unroll
            for (int j = 0; j < 4; j++) {
                ulonglong2 w = ep[j];
                fma2(acc2[2 * j],     v2, w.x);
                fma2(acc2[2 * j + 1], v2, w.y);
            }
        }
    }

    float f[16];
#pragma unroll
    for (int j = 0; j < 8; j++) unpack2(acc2[j], f[2 * j], f[2 * j + 1]);

    int sx = s * SXC + sxl;
    float* dst = blockIdx.z ? g_part : out;
    float4* o4 = (float4*)(dst + ((size_t)(sx * NXY + sy)) * T_TICKS + t0);
    o4[0] = make_float4(f[0],  f[1],  f[2],  f[3]);
    o4[1] = make_float4(f[4],  f[5],  f[6],  f[7]);
    o4[2] = make_float4(f[8],  f[9],  f[10], f[11]);
    o4[3] = make_float4(f[12], f[13], f[14], f[15]);
}

__global__ void k_add(float* __restrict__ out) {
    int i = blockIdx.x * blockDim.x + threadIdx.x;
    float4 a = ((const float4*)out)[i];
    float4 b = ((const float4*)g_part)[i];
    ((float4*)out)[i] = make_float4(a.x + b.x, a.y + b.y, a.z + b.z, a.w + b.w);
}

// ------------------------------------------------------------------
extern "C" void kernel_launch(void* const* d_in, const int* in_sizes, int n_in,
                              void* d_out, int out_size)
{
    const float* si = (const float*)d_in[0];
    const float* zp = (const float*)d_in[1];
    const float* mk = (const float*)d_in[2];
    const float* W1 = (const float*)d_in[3];
    const float* b1 = (const float*)d_in[4];
    const float* W2 = (const float*)d_in[5];
    const float* b2 = (const float*)d_in[6];
    const float* W3 = (const float*)d_in[7];
    const float* b3 = (const float*)d_in[8];
    const float* el = (const float*)d_in[9];
    const float* sl = (const float*)d_in[10];
    float* out = (float*)d_out;                // (48,48,512)

    k_zero   <<<1, NSB>>>();
    k_hist   <<<(NEL + 255) / 256, 256>>>(zp, si, el, sl);
    k_scan   <<<1, NSB>>>();
    k_pre    <<<(NEL + 127) / 128, 256>>>(si, zp, mk, W1, b1, W2, b2, W3, b3, el, sl);
    k_scatter<<<(NEL + 255) / 256, 256>>>(el, sl);
    k_main   <<<dim3(NTILE, NSTRIP, 2), BLK_D>>>(out);
    k_add    <<<(NXY * NXY * T_TICKS / 4) / 256, 256>>>(out);
}

// round 7
// speedup vs baseline: 1.9730x; 1.0855x over previous
#include <cuda_runtime.h>
#include <cuda_bf16.h>

#define NEL     20000      // B*NE total electrons
#define T_TICKS 512
#define NXY     48
#define TT      16         // ticks per tile
#define NTILE   32         // 512/16
#define SXC     6          // sensor-x rows per strip
#define NSTRIP  8          // 48/6
#define WCUT    9          // temporal truncation half-window
#define NB      128        // z buckets (width 4 ticks)
#define CHUNK   64         // electrons per SMEM pass
#define BLK_D   288        // 6*48 threads
#define NSB     (NSTRIP*NB)   // 1024 (strip,bucket) cells
#define MAXENT  (NEL*8)       // worst-case CSR entries
#define ENTF4   14            // 56 floats per entry record
#define NSPLIT  4
#define VOL     (NXY*NXY*T_TICKS)

// ---- scratch (__device__ globals; no allocation allowed) ----
__device__ float g_gx [NEL * 48];
__device__ float g_cgy[NEL * 48];
__device__ float g_z  [NEL];
__device__ float g_ex [NEL];
__device__ int   g_hist[NB];
__device__ int   g_off [NB + 1];
__device__ int   g_cursor[NB];
__device__ int   g_scount[NSB];
__device__ int   g_soff  [NSB + 1];
__device__ int   g_scur  [NSB];
// entry record: [0..5]=gx slice, [6]=z, [7]=pad, [8..55]=c*gy
__device__ float4 g_ent[MAXENT * ENTF4];
__device__ float  g_part[(NSPLIT - 1) * VOL];

// ---- packed f32x2 helpers ----
__device__ __forceinline__ unsigned long long pack2(float v) {
    unsigned long long r;
    unsigned u = __float_as_uint(v);
    asm("mov.b64 %0, {%1, %1};" : "=l"(r) : "r"(u));
    return r;
}
__device__ __forceinline__ void fma2(unsigned long long& acc,
                                     unsigned long long a, unsigned long long b) {
    asm("fma.rn.f32x2 %0, %1, %2, %0;" : "+l"(acc) : "l"(a), "l"(b));
}
__device__ __forceinline__ void unpack2(unsigned long long p, float& lo, float& hi) {
    unsigned a, b;
    asm("mov.b64 {%0, %1}, %2;" : "=r"(a), "=r"(b) : "l"(p));
    lo = __uint_as_float(a); hi = __uint_as_float(b);
}
__device__ __forceinline__ void cpa16(void* dst_smem, const void* src) {
    unsigned d = (unsigned)__cvta_generic_to_shared(dst_smem);
    asm volatile("cp.async.cg.shared.global [%0], [%1], 16;" :: "r"(d), "l"(src));
}
#define CPA_COMMIT()  asm volatile("cp.async.commit_group;" ::: "memory")
#define CPA_WAIT1()   asm volatile("cp.async.wait_group 1;" ::: "memory")

// ------------------------------------------------------------------
__global__ void k_zero() {
    int t = threadIdx.x;
    g_scount[t] = 0;
    if (t < NB) g_hist[t] = 0;
}

__global__ void k_hist(const float* __restrict__ zp, const float* __restrict__ si,
                       const float* __restrict__ el, const float* __restrict__ sloc) {
    __shared__ float sxlo[NSTRIP], sxhi[NSTRIP];
    if (threadIdx.x < NSTRIP) {
        sxlo[threadIdx.x] = sloc[(threadIdx.x * SXC) * 96];
        sxhi[threadIdx.x] = sloc[(threadIdx.x * SXC + SXC - 1) * 96];
    }
    __syncthreads();
    int i = blockIdx.x * blockDim.x + threadIdx.x;
    if (i >= NEL) return;
    int b = min(max((int)zp[i] >> 2, 0), NB - 1);
    atomicAdd(&g_hist[b], 1);
    float x = si[2 * i];
    float thr = 4.57f * el[0];
#pragma unroll
    for (int s = 0; s < NSTRIP; s++) {
        float d = fmaxf(fmaxf(sxlo[s] - x, x - sxhi[s]), 0.0f);
        if (d < thr) atomicAdd(&g_scount[s * NB + b], 1);
    }
}

__global__ void k_scan() {
    __shared__ int sd[NSB];
    int tid = threadIdx.x;
    int v = g_scount[tid];
    sd[tid] = v; __syncthreads();
    for (int d = 1; d < NSB; d <<= 1) {
        int add = (tid >= d) ? sd[tid - d] : 0;
        __syncthreads();
        sd[tid] += add;
        __syncthreads();
    }
    int inc = sd[tid];
    g_soff[tid] = inc - v;
    g_scur[tid] = inc - v;
    if (tid == NSB - 1) g_soff[NSB] = inc;
    __syncthreads();
    int v2 = (tid < NB) ? g_hist[tid] : 0;
    if (tid < NB) sd[tid] = v2;
    __syncthreads();
    for (int d = 1; d < NB; d <<= 1) {
        int add = (tid >= d && tid < NB) ? sd[tid - d] : 0;
        __syncthreads();
        if (tid < NB) sd[tid] += add;
        __syncthreads();
    }
    if (tid < NB) {
        int i2 = sd[tid];
        g_off[tid] = i2 - v2;
        g_cursor[tid] = i2 - v2;
        if (tid == NB - 1) g_off[NB] = i2;
    }
}

// ------------------------------------------------------------------
// Per-electron precompute. 16 threads per 4 electrons; thread o=tid&15
// owns h2 dims [o*8, o*8+8). 128-thread blocks -> 625 CTAs (occupancy!).
__global__ __launch_bounds__(128) void k_pre(
                      const float* __restrict__ si, const float* __restrict__ zp,
                      const float* __restrict__ mk,
                      const float* __restrict__ W1, const float* __restrict__ b1,
                      const float* __restrict__ W2, const float* __restrict__ b2,
                      const float* __restrict__ W3, const float* __restrict__ b3,
                      const float* __restrict__ el, const float* __restrict__ sloc)
{
    __shared__ float  W1s[128], b1s[64];
    __shared__ float4 W2s4[64 * 32];
    __shared__ float4 b2s4[32], W3s4[32];
    __shared__ float  axs[48], ays[48];
    int tid = threadIdx.x;
    if (tid < 128) W1s[tid] = W1[tid];
    if (tid < 64)  b1s[tid] = b1[tid];
    {
        const float4* w2 = (const float4*)W2;
        for (int i = tid; i < 64 * 32; i += blockDim.x) W2s4[i] = w2[i];
    }
    if (tid < 32) { b2s4[tid] = ((const float4*)b2)[tid]; W3s4[tid] = ((const float4*)W3)[tid]; }
    if (tid < 48) { axs[tid] = sloc[tid * 96]; ays[tid] = sloc[tid * 2 + 1]; }
    __syncthreads();

    int lane = tid & 31;
    int o    = tid & 15;
    int grp  = tid >> 4;                      // 8 groups per CTA
    int gbase = (blockIdx.x * 8 + grp) * 4;   // 4 electrons per group
    if (gbase >= NEL) return;

    float xs[4], ys[4];
#pragma unroll
    for (int i = 0; i < 4; i++) { xs[i] = si[2 * (gbase + i)]; ys[i] = si[2 * (gbase + i) + 1]; }

    float4 h2[4][2];
#pragma unroll
    for (int e = 0; e < 4; e++)
#pragma unroll
        for (int q = 0; q < 2; q++) h2[e][q] = b2s4[o * 2 + q];

    for (int k = 0; k < 64; k++) {
        float w1a = W1s[k], w1b = W1s[64 + k], bb = b1s[k];
        float h1[4];
#pragma unroll
        for (int e = 0; e < 4; e++)
            h1[e] = fmaxf(fmaf(xs[e], w1a, fmaf(ys[e], w1b, bb)), 0.0f);
        const float4* wp = &W2s4[k * 32 + o * 2];
#pragma unroll
        for (int q = 0; q < 2; q++) {
            float4 w = wp[q];
#pragma unroll
            for (int e = 0; e < 4; e++) {
                h2[e][q].x = fmaf(h1[e], w.x, h2[e][q].x);
                h2[e][q].y = fmaf(h1[e], w.y, h2[e][q].y);
                h2[e][q].z = fmaf(h1[e], w.z, h2[e][q].z);
                h2[e][q].w = fmaf(h1[e], w.w, h2[e][q].w);
            }
        }
    }

    float rp[4] = {0.f, 0.f, 0.f, 0.f};
#pragma unroll
    for (int q = 0; q < 2; q++) {
        float4 w = W3s4[o * 2 + q];
#pragma unroll
        for (int e = 0; e < 4; e++) {
            rp[e] = fmaf(fmaxf(h2[e][q].x, 0.f), w.x, rp[e]);
            rp[e] = fmaf(fmaxf(h2[e][q].y, 0.f), w.y, rp[e]);
            rp[e] = fmaf(fmaxf(h2[e][q].z, 0.f), w.z, rp[e]);
            rp[e] = fmaf(fmaxf(h2[e][q].w, 0.f), w.w, rp[e]);
        }
    }
#pragma unroll
    for (int d = 1; d < 16; d <<= 1)
#pragma unroll
        for (int e = 0; e < 4; e++)
            rp[e] += __shfl_xor_sync(0xffffffffu, rp[e], d);

    float es = el[0];
    float inv = -0.5f / (es * es);
    float cnorm = (100.0f / (es * 2.5066f)) * 0.17841241161f;

    // 4 lanes per electron: r=0 gx[0:24), r=1 gx[24:48), r=2 gy[0:24), r=3 gy[24:48)
    int myE = o >> 2;
    int r   = o & 3;
    int ei  = gbase + myE;
    float resp = rp[myE] + b3[0];
    float c = resp * mk[ei] * cnorm;
    float z = zp[ei];
    float x = xs[myE], y = ys[myE];

    int posv = 0;
    if (r == 0) {
        int b = min(max((int)z >> 2, 0), NB - 1);
        posv = atomicAdd(&g_cursor[b], 1);
    }
    int pos = __shfl_sync(0xffffffffu, posv, lane & ~3);

    if (r < 2) {
        float4* pgx = (float4*)(g_gx + (size_t)pos * 48);
#pragma unroll
        for (int q = 0; q < 6; q++) {
            int qq = r * 6 + q;
            float d0 = x - axs[4 * qq + 0], d1 = x - axs[4 * qq + 1];
            float d2 = x - axs[4 * qq + 2], d3 = x - axs[4 * qq + 3];
            pgx[qq] = make_float4(__expf(d0 * d0 * inv), __expf(d1 * d1 * inv),
                                  __expf(d2 * d2 * inv), __expf(d3 * d3 * inv));
        }
        if (r == 0) { g_z[pos] = z; g_ex[pos] = x; }
    } else {
        float4* pgy = (float4*)(g_cgy + (size_t)pos * 48);
#pragma unroll
        for (int q = 0; q < 6; q++) {
            int qq = (r - 2) * 6 + q;
            float d0 = y - ays[4 * qq + 0], d1 = y - ays[4 * qq + 1];
            float d2 = y - ays[4 * qq + 2], d3 = y - ays[4 * qq + 3];
            pgy[qq] = make_float4(c * __expf(d0 * d0 * inv), c * __expf(d1 * d1 * inv),
                                  c * __expf(d2 * d2 * inv), c * __expf(d3 * d3 * inv));
        }
    }
}

// ------------------------------------------------------------------
// Build flat per-entry records (contiguous; staging in k_main is a
// straight cp.async burst, no gather dependency).
__global__ void k_scatter(const float* __restrict__ el, const float* __restrict__ sloc) {
    __shared__ float sxlo[NSTRIP], sxhi[NSTRIP];
    if (threadIdx.x < NSTRIP) {
        sxlo[threadIdx.x] = sloc[(threadIdx.x * SXC) * 96];
        sxhi[threadIdx.x] = sloc[(threadIdx.x * SXC + SXC - 1) * 96];
    }
    __syncthreads();
    int pos = blockIdx.x * blockDim.x + threadIdx.x;
    if (pos >= NEL) return;
    float x = g_ex[pos], z = g_z[pos];
    int b = min(max((int)z >> 2, 0), NB - 1);
    float thr = 4.57f * el[0];

    float4 gy[12];
    const float4* gys = (const float4*)(g_cgy + (size_t)pos * 48);
#pragma unroll
    for (int j = 0; j < 12; j++) gy[j] = gys[j];
    const float* gxr = g_gx + (size_t)pos * 48;

#pragma unroll
    for (int s = 0; s < NSTRIP; s++) {
        float d = fmaxf(fmaxf(sxlo[s] - x, x - sxhi[s]), 0.0f);
        if (d < thr) {
            int q = atomicAdd(&g_scur[s * NB + b], 1);
            float4* ent = &g_ent[(size_t)q * ENTF4];
            ent[0] = make_float4(gxr[s * SXC + 0], gxr[s * SXC + 1],
                                 gxr[s * SXC + 2], gxr[s * SXC + 3]);
            ent[1] = make_float4(gxr[s * SXC + 4], gxr[s * SXC + 5], z, 0.0f);
#pragma unroll
            for (int j = 0; j < 12; j++) ent[2 + j] = gy[j];
        }
    }
}

// ------------------------------------------------------------------
// Main accumulation: CTA = (t-tile, strip, split4). Double-buffered
// cp.async staging of contiguous entry records; packed-f32x2 inner loop.
__global__ __launch_bounds__(BLK_D) void k_main(float* __restrict__ out)
{
    __shared__ float4     s_ent[2][CHUNK * ENTF4];
    __shared__ ulonglong2 s_ev2[2][CHUNK * 4];

    int tid = threadIdx.x;
    int t0  = blockIdx.x * TT;
    int s   = blockIdx.y;
    int sxl = tid / 48;
    int sy  = tid - sxl * 48;

    int blo = max(t0 - WCUT, 0) >> 2;
    int bhi = min(t0 + TT - 1 + WCUT, T_TICKS - 1) >> 2;
    int rb = g_soff[s * NB + blo], re = g_soff[s * NB + bhi + 1];
    int len = re - rb;
    int part = (len + NSPLIT - 1) / NSPLIT;
    int cb = rb + blockIdx.z * part;
    int ce = min(cb + part, re);
    int nch = (ce > cb) ? (ce - cb + CHUNK - 1) / CHUNK : 0;

    unsigned long long acc2[8];
#pragma unroll
    for (int j = 0; j < 8; j++) acc2[j] = 0ull;

    // prefetch chunk 0
    if (nch > 0) {
        int cnt0 = min(CHUNK, ce - cb);
        const float4* src = &g_ent[(size_t)cb * ENTF4];
        for (int i = tid; i < cnt0 * ENTF4; i += BLK_D)
            cpa16(&s_ent[0][i], &src[i]);
    }
    CPA_COMMIT();

    for (int ch = 0; ch < nch; ch++) {
        int c0  = cb + ch * CHUNK;
        int cnt = min(CHUNK, ce - c0);
        int buf = ch & 1;

        __syncthreads();                    // compute(ch-1) complete (buf^1 free)
        if (ch + 1 < nch) {                 // issue stage(ch+1) before waiting on ch
            int c1 = c0 + CHUNK;
            int cnt1 = min(CHUNK, ce - c1);
            const float4* src = &g_ent[(size_t)c1 * ENTF4];
            for (int i = tid; i < cnt1 * ENTF4; i += BLK_D)
                cpa16(&s_ent[buf ^ 1][i], &src[i]);
        }
        CPA_COMMIT();
        CPA_WAIT1();                        // stage(ch) complete
        __syncthreads();

        // time-gaussian weights for this tile
        float* evf = (float*)s_ev2[buf];
        for (int idx = tid; idx < cnt * TT; idx += BLK_D) {
            int e = idx >> 4;
            int k = idx & (TT - 1);
            float z = ((const float*)&s_ent[buf][e * ENTF4])[6];
            float d = (float)(t0 + k) - z;
            evf[idx] = __expf(-0.1f * d * d);
        }
        __syncthreads();

        const ulonglong2* evb = s_ev2[buf];
#pragma unroll 2
        for (int e = 0; e < cnt; e++) {
            const float* ep = (const float*)&s_ent[buf][e * ENTF4];
            float v = ep[sxl] * ep[8 + sy];
            unsigned long long v2 = pack2(v);
            const ulonglong2* wp = &evb[e * 4];
#pragma unroll
            for (int j = 0; j < 4; j++) {
                ulonglong2 w = wp[j];
                fma2(acc2[2 * j],     v2, w.x);
                fma2(acc2[2 * j + 1], v2, w.y);
            }
        }
    }

    float f[16];
#pragma unroll
    for (int j = 0; j < 8; j++) unpack2(acc2[j], f[2 * j], f[2 * j + 1]);

    int sx = s * SXC + sxl;
    float* dst = blockIdx.z ? (g_part + (size_t)(blockIdx.z - 1) * VOL) : out;
    float4* o4 = (float4*)(dst + ((size_t)(sx * NXY + sy)) * T_TICKS + t0);
    o4[0] = make_float4(f[0],  f[1],  f[2],  f[3]);
    o4[1] = make_float4(f[4],  f[5],  f[6],  f[7]);
    o4[2] = make_float4(f[8],  f[9],  f[10], f[11]);
    o4[3] = make_float4(f[12], f[13], f[14], f[15]);
}

__global__ void k_add(float* __restrict__ out) {
    int i = blockIdx.x * blockDim.x + threadIdx.x;
    float4 a = ((const float4*)out)[i];
    float4 b0 = ((const float4*)g_part)[i];
    float4 b1 = ((const float4*)(g_part + VOL))[i];
    float4 b2 = ((const float4*)(g_part + 2 * VOL))[i];
    ((float4*)out)[i] = make_float4(a.x + b0.x + b1.x + b2.x,
                                    a.y + b0.y + b1.y + b2.y,
                                    a.z + b0.z + b1.z + b2.z,
                                    a.w + b0.w + b1.w + b2.w);
}

// ------------------------------------------------------------------
extern "C" void kernel_launch(void* const* d_in, const int* in_sizes, int n_in,
                              void* d_out, int out_size)
{
    const float* si = (const float*)d_in[0];
    const float* zp = (const float*)d_in[1];
    const float* mk = (const float*)d_in[2];
    const float* W1 = (const float*)d_in[3];
    const float* b1 = (const float*)d_in[4];
    const float* W2 = (const float*)d_in[5];
    const float* b2 = (const float*)d_in[6];
    const float* W3 = (const float*)d_in[7];
    const float* b3 = (const float*)d_in[8];
    const float* el = (const float*)d_in[9];
    const float* sl = (const float*)d_in[10];
    float* out = (float*)d_out;                // (48,48,512)

    k_zero   <<<1, NSB>>>();
    k_hist   <<<(NEL + 255) / 256, 256>>>(zp, si, el, sl);
    k_scan   <<<1, NSB>>>();
    k_pre    <<<(NEL + 31) / 32, 128>>>(si, zp, mk, W1, b1, W2, b2, W3, b3, el, sl);
    k_scatter<<<(NEL + 255) / 256, 256>>>(el, sl);
    k_main   <<<dim3(NTILE, NSTRIP, NSPLIT), BLK_D>>>(out);
    k_add    <<<(VOL / 4) / 256, 256>>>(out);
}

// round 8
// speedup vs baseline: 2.2460x; 1.1384x over previous
#include <cuda_runtime.h>
#include <cuda_bf16.h>

#define NEL     20000      // B*NE total electrons
#define T_TICKS 512
#define NXY     48
#define TT      8          // ticks per tile
#define NTILE   64         // 512/8
#define SXC     6          // sensor-x rows per strip
#define NSTRIP  8          // 48/6
#define WCUT    9          // temporal truncation half-window
#define NB      128        // z buckets (width 4 ticks)
#define CHUNK   64         // electrons per SMEM pass
#define BLK_D   160        // 5 warps; 144 active compute threads
#define ACT_D   144        // 6 sx rows x 24 sensor-pair columns
#define NSB     (NSTRIP*NB)
#define MAXENT  (NEL*8)
#define ENTF4   14            // 56 floats per entry record
#define NSPLIT  4
#define VOL     (NXY*NXY*T_TICKS)

// ---- scratch (__device__ globals; no allocation allowed) ----
__device__ float g_gx [NEL * 48];
__device__ float g_cgy[NEL * 48];
__device__ float g_z  [NEL];
__device__ float g_ex [NEL];
__device__ int   g_hist[NB];
__device__ int   g_off [NB + 1];
__device__ int   g_cursor[NB];
__device__ int   g_scount[NSB];
__device__ int   g_soff  [NSB + 1];
__device__ int   g_scur  [NSB];
// entry record: [0..5]=gx slice, [6]=z, [7]=pad, [8..55]=c*gy
__device__ float4 g_ent[MAXENT * ENTF4];
__device__ float  g_part[(NSPLIT - 1) * VOL];

// ---- packed f32x2 helpers ----
__device__ __forceinline__ unsigned long long pack2(float v) {
    unsigned long long r;
    unsigned u = __float_as_uint(v);
    asm("mov.b64 %0, {%1, %1};" : "=l"(r) : "r"(u));
    return r;
}
__device__ __forceinline__ void fma2(unsigned long long& acc,
                                     unsigned long long a, unsigned long long b) {
    asm("fma.rn.f32x2 %0, %1, %2, %0;" : "+l"(acc) : "l"(a), "l"(b));
}
__device__ __forceinline__ void unpack2(unsigned long long p, float& lo, float& hi) {
    unsigned a, b;
    asm("mov.b64 {%0, %1}, %2;" : "=r"(a), "=r"(b) : "l"(p));
    lo = __uint_as_float(a); hi = __uint_as_float(b);
}
__device__ __forceinline__ void cpa16(void* dst_smem, const void* src) {
    unsigned d = (unsigned)__cvta_generic_to_shared(dst_smem);
    asm volatile("cp.async.cg.shared.global [%0], [%1], 16;" :: "r"(d), "l"(src));
}
#define CPA_COMMIT()  asm volatile("cp.async.commit_group;" ::: "memory")
#define CPA_WAIT1()   asm volatile("cp.async.wait_group 1;" ::: "memory")

// ------------------------------------------------------------------
__global__ void k_zero() {
    int t = threadIdx.x;
    g_scount[t] = 0;
    if (t < NB) g_hist[t] = 0;
}

__global__ void k_hist(const float* __restrict__ zp, const float* __restrict__ si,
                       const float* __restrict__ el, const float* __restrict__ sloc) {
    __shared__ float sxlo[NSTRIP], sxhi[NSTRIP];
    if (threadIdx.x < NSTRIP) {
        sxlo[threadIdx.x] = sloc[(threadIdx.x * SXC) * 96];
        sxhi[threadIdx.x] = sloc[(threadIdx.x * SXC + SXC - 1) * 96];
    }
    __syncthreads();
    int i = blockIdx.x * blockDim.x + threadIdx.x;
    if (i >= NEL) return;
    int b = min(max((int)zp[i] >> 2, 0), NB - 1);
    atomicAdd(&g_hist[b], 1);
    float x = si[2 * i];
    float thr = 4.57f * el[0];
#pragma unroll
    for (int s = 0; s < NSTRIP; s++) {
        float d = fmaxf(fmaxf(sxlo[s] - x, x - sxhi[s]), 0.0f);
        if (d < thr) atomicAdd(&g_scount[s * NB + b], 1);
    }
}

__global__ void k_scan() {
    __shared__ int sd[NSB];
    int tid = threadIdx.x;
    int v = g_scount[tid];
    sd[tid] = v; __syncthreads();
    for (int d = 1; d < NSB; d <<= 1) {
        int add = (tid >= d) ? sd[tid - d] : 0;
        __syncthreads();
        sd[tid] += add;
        __syncthreads();
    }
    int inc = sd[tid];
    g_soff[tid] = inc - v;
    g_scur[tid] = inc - v;
    if (tid == NSB - 1) g_soff[NSB] = inc;
    __syncthreads();
    int v2 = (tid < NB) ? g_hist[tid] : 0;
    if (tid < NB) sd[tid] = v2;
    __syncthreads();
    for (int d = 1; d < NB; d <<= 1) {
        int add = (tid >= d && tid < NB) ? sd[tid - d] : 0;
        __syncthreads();
        if (tid < NB) sd[tid] += add;
        __syncthreads();
    }
    if (tid < NB) {
        int i2 = sd[tid];
        g_off[tid] = i2 - v2;
        g_cursor[tid] = i2 - v2;
        if (tid == NB - 1) g_off[NB] = i2;
    }
}

// ------------------------------------------------------------------
// Per-electron precompute. 16 threads per 2 electrons; thread o=tid&15
// owns h2 dims [o*8, o*8+8). grid=1250 CTAs -> ~8.4 CTAs/SM.
__global__ __launch_bounds__(128) void k_pre(
                      const float* __restrict__ si, const float* __restrict__ zp,
                      const float* __restrict__ mk,
                      const float* __restrict__ W1, const float* __restrict__ b1,
                      const float* __restrict__ W2, const float* __restrict__ b2,
                      const float* __restrict__ W3, const float* __restrict__ b3,
                      const float* __restrict__ el, const float* __restrict__ sloc)
{
    __shared__ float  W1s[128], b1s[64];
    __shared__ float4 W2s4[64 * 32];
    __shared__ float4 b2s4[32], W3s4[32];
    __shared__ float  axs[48], ays[48];
    int tid = threadIdx.x;
    if (tid < 128) W1s[tid] = W1[tid];
    if (tid < 64)  b1s[tid] = b1[tid];
    {
        const float4* w2 = (const float4*)W2;
        for (int i = tid; i < 64 * 32; i += blockDim.x) W2s4[i] = w2[i];
    }
    if (tid < 32) { b2s4[tid] = ((const float4*)b2)[tid]; W3s4[tid] = ((const float4*)W3)[tid]; }
    if (tid < 48) { axs[tid] = sloc[tid * 96]; ays[tid] = sloc[tid * 2 + 1]; }
    __syncthreads();

    int lane = tid & 31;
    int o    = tid & 15;
    int grp  = tid >> 4;                      // 8 groups per CTA
    int gbase = (blockIdx.x * 8 + grp) * 2;   // 2 electrons per group
    if (gbase >= NEL) return;

    float xs[2], ys[2];
#pragma unroll
    for (int i = 0; i < 2; i++) { xs[i] = si[2 * (gbase + i)]; ys[i] = si[2 * (gbase + i) + 1]; }

    float4 h2[2][2];
#pragma unroll
    for (int e = 0; e < 2; e++)
#pragma unroll
        for (int q = 0; q < 2; q++) h2[e][q] = b2s4[o * 2 + q];

    for (int k = 0; k < 64; k++) {
        float w1a = W1s[k], w1b = W1s[64 + k], bb = b1s[k];
        float h1[2];
#pragma unroll
        for (int e = 0; e < 2; e++)
            h1[e] = fmaxf(fmaf(xs[e], w1a, fmaf(ys[e], w1b, bb)), 0.0f);
        const float4* wp = &W2s4[k * 32 + o * 2];
#pragma unroll
        for (int q = 0; q < 2; q++) {
            float4 w = wp[q];
#pragma unroll
            for (int e = 0; e < 2; e++) {
                h2[e][q].x = fmaf(h1[e], w.x, h2[e][q].x);
                h2[e][q].y = fmaf(h1[e], w.y, h2[e][q].y);
                h2[e][q].z = fmaf(h1[e], w.z, h2[e][q].z);
                h2[e][q].w = fmaf(h1[e], w.w, h2[e][q].w);
            }
        }
    }

    float rp[2] = {0.f, 0.f};
#pragma unroll
    for (int q = 0; q < 2; q++) {
        float4 w = W3s4[o * 2 + q];
#pragma unroll
        for (int e = 0; e < 2; e++) {
            rp[e] = fmaf(fmaxf(h2[e][q].x, 0.f), w.x, rp[e]);
            rp[e] = fmaf(fmaxf(h2[e][q].y, 0.f), w.y, rp[e]);
            rp[e] = fmaf(fmaxf(h2[e][q].z, 0.f), w.z, rp[e]);
            rp[e] = fmaf(fmaxf(h2[e][q].w, 0.f), w.w, rp[e]);
        }
    }
#pragma unroll
    for (int d = 1; d < 16; d <<= 1)
#pragma unroll
        for (int e = 0; e < 2; e++)
            rp[e] += __shfl_xor_sync(0xffffffffu, rp[e], d);

    float es = el[0];
    float inv = -0.5f / (es * es);
    float cnorm = (100.0f / (es * 2.5066f)) * 0.17841241161f;

    // 8 lanes per electron: r=0..3 gx quarters, r=4..7 gy quarters
    int myE = o >> 3;
    int r   = o & 7;
    int ei  = gbase + myE;
    float resp = rp[myE] + b3[0];
    float c = resp * mk[ei] * cnorm;
    float z = zp[ei];
    float x = xs[myE], y = ys[myE];

    int posv = 0;
    if (r == 0) {
        int b = min(max((int)z >> 2, 0), NB - 1);
        posv = atomicAdd(&g_cursor[b], 1);
    }
    int pos = __shfl_sync(0xffffffffu, posv, lane & ~7);

    if (r < 4) {
        float4* pgx = (float4*)(g_gx + (size_t)pos * 48);
#pragma unroll
        for (int q = 0; q < 3; q++) {
            int qq = r * 3 + q;
            float d0 = x - axs[4 * qq + 0], d1 = x - axs[4 * qq + 1];
            float d2 = x - axs[4 * qq + 2], d3 = x - axs[4 * qq + 3];
            pgx[qq] = make_float4(__expf(d0 * d0 * inv), __expf(d1 * d1 * inv),
                                  __expf(d2 * d2 * inv), __expf(d3 * d3 * inv));
        }
        if (r == 0) { g_z[pos] = z; g_ex[pos] = x; }
    } else {
        float4* pgy = (float4*)(g_cgy + (size_t)pos * 48);
#pragma unroll
        for (int q = 0; q < 3; q++) {
            int qq = (r - 4) * 3 + q;
            float d0 = y - ays[4 * qq + 0], d1 = y - ays[4 * qq + 1];
            float d2 = y - ays[4 * qq + 2], d3 = y - ays[4 * qq + 3];
            pgy[qq] = make_float4(c * __expf(d0 * d0 * inv), c * __expf(d1 * d1 * inv),
                                  c * __expf(d2 * d2 * inv), c * __expf(d3 * d3 * inv));
        }
    }
}

// ------------------------------------------------------------------
// Build flat per-entry records (contiguous; staging in k_main is a
// straight cp.async burst, no gather dependency).
__global__ void k_scatter(const float* __restrict__ el, const float* __restrict__ sloc) {
    __shared__ float sxlo[NSTRIP], sxhi[NSTRIP];
    if (threadIdx.x < NSTRIP) {
        sxlo[threadIdx.x] = sloc[(threadIdx.x * SXC) * 96];
        sxhi[threadIdx.x] = sloc[(threadIdx.x * SXC + SXC - 1) * 96];
    }
    __syncthreads();
    int pos = blockIdx.x * blockDim.x + threadIdx.x;
    if (pos >= NEL) return;
    float x = g_ex[pos], z = g_z[pos];
    int b = min(max((int)z >> 2, 0), NB - 1);
    float thr = 4.57f * el[0];

    float4 gy[12];
    const float4* gys = (const float4*)(g_cgy + (size_t)pos * 48);
#pragma unroll
    for (int j = 0; j < 12; j++) gy[j] = gys[j];
    const float* gxr = g_gx + (size_t)pos * 48;

#pragma unroll
    for (int s = 0; s < NSTRIP; s++) {
        float d = fmaxf(fmaxf(sxlo[s] - x, x - sxhi[s]), 0.0f);
        if (d < thr) {
            int q = atomicAdd(&g_scur[s * NB + b], 1);
            float4* ent = &g_ent[(size_t)q * ENTF4];
            ent[0] = make_float4(gxr[s * SXC + 0], gxr[s * SXC + 1],
                                 gxr[s * SXC + 2], gxr[s * SXC + 3]);
            ent[1] = make_float4(gxr[s * SXC + 4], gxr[s * SXC + 5], z, 0.0f);
#pragma unroll
            for (int j = 0; j < 12; j++) ent[2 + j] = gy[j];
        }
    }
}

// ------------------------------------------------------------------
// Main accumulation: CTA = (t-tile of 8 ticks, strip, split4).
// 144 active threads, each owning 2 sensors (sy=2q, 2q+1): gy via one
// LDS.64, shared ev broadcasts, dual packed-f32x2 accumulators.
__global__ __launch_bounds__(BLK_D) void k_main(float* __restrict__ out)
{
    __shared__ float4     s_ent[2][CHUNK * ENTF4];
    __shared__ ulonglong2 s_ev2[CHUNK * 2];

    int tid = threadIdx.x;
    int t0  = blockIdx.x * TT;
    int s   = blockIdx.y;
    int sxl = tid / 24;          // 0..5 for active threads
    int q   = tid - sxl * 24;    // sensor-pair column 0..23

    int blo = max(t0 - WCUT, 0) >> 2;
    int bhi = min(t0 + TT - 1 + WCUT, T_TICKS - 1) >> 2;
    int rb = g_soff[s * NB + blo], re = g_soff[s * NB + bhi + 1];
    int len = re - rb;
    int part = (len + NSPLIT - 1) / NSPLIT;
    int cb = rb + blockIdx.z * part;
    int ce = min(cb + part, re);
    int nch = (ce > cb) ? (ce - cb + CHUNK - 1) / CHUNK : 0;

    unsigned long long aa[4], ab[4];
#pragma unroll
    for (int j = 0; j < 4; j++) { aa[j] = 0ull; ab[j] = 0ull; }

    // prefetch chunk 0
    if (nch > 0) {
        int cnt0 = min(CHUNK, ce - cb);
        const float4* src = &g_ent[(size_t)cb * ENTF4];
        for (int i = tid; i < cnt0 * ENTF4; i += BLK_D)
            cpa16(&s_ent[0][i], &src[i]);
    }
    CPA_COMMIT();

    for (int ch = 0; ch < nch; ch++) {
        int c0  = cb + ch * CHUNK;
        int cnt = min(CHUNK, ce - c0);
        int buf = ch & 1;

        __syncthreads();                    // compute(ch-1) done: buf^1 + s_ev2 free
        if (ch + 1 < nch) {                 // stage(ch+1) before waiting on ch
            int c1 = c0 + CHUNK;
            int cnt1 = min(CHUNK, ce - c1);
            const float4* src = &g_ent[(size_t)c1 * ENTF4];
            for (int i = tid; i < cnt1 * ENTF4; i += BLK_D)
                cpa16(&s_ent[buf ^ 1][i], &src[i]);
        }
        CPA_COMMIT();
        CPA_WAIT1();                        // stage(ch) complete
        __syncthreads();

        // time-gaussian weights for this 8-tick tile
        float* evf = (float*)s_ev2;
        for (int idx = tid; idx < cnt * TT; idx += BLK_D) {
            int e = idx >> 3;
            int k = idx & (TT - 1);
            float z = ((const float*)&s_ent[buf][e * ENTF4])[6];
            float d = (float)(t0 + k) - z;
            evf[idx] = __expf(-0.1f * d * d);
        }
        __syncthreads();

        if (tid < ACT_D) {
#pragma unroll 2
            for (int e = 0; e < cnt; e++) {
                const float* ep = (const float*)&s_ent[buf][e * ENTF4];
                float gxv = ep[sxl];
                float2 gy2 = *(const float2*)(ep + 8 + 2 * q);
                unsigned long long va2 = pack2(gxv * gy2.x);
                unsigned long long vb2 = pack2(gxv * gy2.y);
                ulonglong2 w0 = s_ev2[e * 2 + 0];
                ulonglong2 w1 = s_ev2[e * 2 + 1];
                fma2(aa[0], va2, w0.x); fma2(ab[0], vb2, w0.x);
                fma2(aa[1], va2, w0.y); fma2(ab[1], vb2, w0.y);
                fma2(aa[2], va2, w1.x); fma2(ab[2], vb2, w1.x);
                fma2(aa[3], va2, w1.y); fma2(ab[3], vb2, w1.y);
            }
        }
    }

    if (tid < ACT_D) {
        float fa[8], fb[8];
#pragma unroll
        for (int j = 0; j < 4; j++) {
            unpack2(aa[j], fa[2 * j], fa[2 * j + 1]);
            unpack2(ab[j], fb[2 * j], fb[2 * j + 1]);
        }
        int sx = s * SXC + sxl;
        int sy = 2 * q;
        float* dst = blockIdx.z ? (g_part + (size_t)(blockIdx.z - 1) * VOL) : out;
        float4* oa = (float4*)(dst + ((size_t)(sx * NXY + sy)) * T_TICKS + t0);
        float4* ob = (float4*)(dst + ((size_t)(sx * NXY + sy + 1)) * T_TICKS + t0);
        oa[0] = make_float4(fa[0], fa[1], fa[2], fa[3]);
        oa[1] = make_float4(fa[4], fa[5], fa[6], fa[7]);
        ob[0] = make_float4(fb[0], fb[1], fb[2], fb[3]);
        ob[1] = make_float4(fb[4], fb[5], fb[6], fb[7]);
    }
}

__global__ void k_add(float* __restrict__ out) {
    int i = blockIdx.x * blockDim.x + threadIdx.x;
    float4 a = ((const float4*)out)[i];
    float4 b0 = ((const float4*)g_part)[i];
    float4 b1 = ((const float4*)(g_part + VOL))[i];
    float4 b2 = ((const float4*)(g_part + 2 * VOL))[i];
    ((float4*)out)[i] = make_float4(a.x + b0.x + b1.x + b2.x,
                                    a.y + b0.y + b1.y + b2.y,
                                    a.z + b0.z + b1.z + b2.z,
                                    a.w + b0.w + b1.w + b2.w);
}

// ------------------------------------------------------------------
extern "C" void kernel_launch(void* const* d_in, const int* in_sizes, int n_in,
                              void* d_out, int out_size)
{
    const float* si = (const float*)d_in[0];
    const float* zp = (const float*)d_in[1];
    const float* mk = (const float*)d_in[2];
    const float* W1 = (const float*)d_in[3];
    const float* b1 = (const float*)d_in[4];
    const float* W2 = (const float*)d_in[5];
    const float* b2 = (const float*)d_in[6];
    const float* W3 = (const float*)d_in[7];
    const float* b3 = (const float*)d_in[8];
    const float* el = (const float*)d_in[9];
    const float* sl = (const float*)d_in[10];
    float* out = (float*)d_out;                // (48,48,512)

    k_zero   <<<1, NSB>>>();
    k_hist   <<<(NEL + 255) / 256, 256>>>(zp, si, el, sl);
    k_scan   <<<1, NSB>>>();
    k_pre    <<<(NEL + 15) / 16, 128>>>(si, zp, mk, W1, b1, W2, b2, W3, b3, el, sl);
    k_scatter<<<(NEL + 255) / 256, 256>>>(el, sl);
    k_main   <<<dim3(NTILE, NSTRIP, NSPLIT), BLK_D>>>(out);
    k_add    <<<(VOL / 4) / 256, 256>>>(out);
}

// round 9
// speedup vs baseline: 2.5618x; 1.1406x over previous
#include <cuda_runtime.h>
#include <cuda_bf16.h>

#define NEL     20000      // B*NE total electrons
#define T_TICKS 512
#define NXY     48
#define TT      8          // ticks per tile
#define NTILE   64         // 512/8
#define SXC     6          // sensor-x rows per strip
#define NSTRIP  8          // 48/6
#define WCUT    9          // temporal truncation half-window
#define NB      128        // z buckets (width 4 ticks)
#define CHUNK   64         // electrons per SMEM pass
#define BLK_D   160        // 5 warps; 144 active compute threads
#define ACT_D   144        // 6 sx rows x 24 sensor-pair columns
#define NSB     (NSTRIP*NB)
#define MAXENT  (NEL*8)
#define ENTF4   14            // 56 floats per entry record (224B)
#define ENTB    224
#define NSPLIT  4
#define VOL     (NXY*NXY*T_TICKS)

// ---- scratch (__device__ globals; no allocation allowed) ----
__device__ float g_gx [NEL * 48];
__device__ float g_cgy[NEL * 48];
__device__ float g_z  [NEL];
__device__ float g_ex [NEL];
__device__ int   g_hist[NB];
__device__ int   g_off [NB + 1];
__device__ int   g_cursor[NB];
__device__ int   g_scount[NSB];
__device__ int   g_soff  [NSB + 1];
__device__ int   g_scur  [NSB];
// entry record: [0..5]=gx slice, [6]=z, [7]=pad, [8..55]=c*gy
__device__ float4 g_ent[MAXENT * ENTF4];
__device__ float  g_part[(NSPLIT - 1) * VOL];

// ---- packed f32x2 helpers ----
__device__ __forceinline__ unsigned long long pack2(float v) {
    unsigned long long r;
    unsigned u = __float_as_uint(v);
    asm("mov.b64 %0, {%1, %1};" : "=l"(r) : "r"(u));
    return r;
}
__device__ __forceinline__ void fma2(unsigned long long& acc,
                                     unsigned long long a, unsigned long long b) {
    asm("fma.rn.f32x2 %0, %1, %2, %0;" : "+l"(acc) : "l"(a), "l"(b));
}
__device__ __forceinline__ void unpack2(unsigned long long p, float& lo, float& hi) {
    unsigned a, b;
    asm("mov.b64 {%0, %1}, %2;" : "=r"(a), "=r"(b) : "l"(p));
    lo = __uint_as_float(a); hi = __uint_as_float(b);
}

// ---- mbarrier / bulk-copy helpers ----
__device__ __forceinline__ unsigned smem_u32(const void* p) {
    return (unsigned)__cvta_generic_to_shared(p);
}
__device__ __forceinline__ void mbar_init(unsigned mbar, unsigned cnt) {
    asm volatile("mbarrier.init.shared.b64 [%0], %1;" :: "r"(mbar), "r"(cnt) : "memory");
}
__device__ __forceinline__ void mbar_expect_tx(unsigned mbar, unsigned bytes) {
    asm volatile("mbarrier.arrive.expect_tx.shared.b64 _, [%0], %1;"
                 :: "r"(mbar), "r"(bytes) : "memory");
}
__device__ __forceinline__ void bulk_g2s(unsigned dst, const void* src,
                                         unsigned bytes, unsigned mbar) {
    asm volatile("cp.async.bulk.shared::cta.global.mbarrier::complete_tx::bytes "
                 "[%0], [%1], %2, [%3];"
                 :: "r"(dst), "l"(src), "r"(bytes), "r"(mbar) : "memory");
}
__device__ __forceinline__ void mbar_wait(unsigned mbar, unsigned parity) {
    asm volatile(
        "{\n\t"
        ".reg .pred P1;\n\t"
        "WAIT_LOOP_%=:\n\t"
        "mbarrier.try_wait.parity.acquire.cta.shared::cta.b64 P1, [%0], %1, 0x989680;\n\t"
        "@P1 bra.uni WAIT_DONE_%=;\n\t"
        "bra.uni WAIT_LOOP_%=;\n\t"
        "WAIT_DONE_%=:\n\t"
        "}"
        :: "r"(mbar), "r"(parity) : "memory");
}

// ------------------------------------------------------------------
__global__ void k_zero() {
    int t = threadIdx.x;
    g_scount[t] = 0;
    if (t < NB) g_hist[t] = 0;
}

__global__ void k_hist(const float* __restrict__ zp, const float* __restrict__ si,
                       const float* __restrict__ el, const float* __restrict__ sloc) {
    __shared__ float sxlo[NSTRIP], sxhi[NSTRIP];
    if (threadIdx.x < NSTRIP) {
        sxlo[threadIdx.x] = sloc[(threadIdx.x * SXC) * 96];
        sxhi[threadIdx.x] = sloc[(threadIdx.x * SXC + SXC - 1) * 96];
    }
    __syncthreads();
    int i = blockIdx.x * blockDim.x + threadIdx.x;
    if (i >= NEL) return;
    int b = min(max((int)zp[i] >> 2, 0), NB - 1);
    atomicAdd(&g_hist[b], 1);
    float x = si[2 * i];
    float thr = 4.57f * el[0];
#pragma unroll
    for (int s = 0; s < NSTRIP; s++) {
        float d = fmaxf(fmaxf(sxlo[s] - x, x - sxhi[s]), 0.0f);
        if (d < thr) atomicAdd(&g_scount[s * NB + b], 1);
    }
}

__global__ void k_scan() {
    __shared__ int sd[NSB];
    int tid = threadIdx.x;
    int v = g_scount[tid];
    sd[tid] = v; __syncthreads();
    for (int d = 1; d < NSB; d <<= 1) {
        int add = (tid >= d) ? sd[tid - d] : 0;
        __syncthreads();
        sd[tid] += add;
        __syncthreads();
    }
    int inc = sd[tid];
    g_soff[tid] = inc - v;
    g_scur[tid] = inc - v;
    if (tid == NSB - 1) g_soff[NSB] = inc;
    __syncthreads();
    int v2 = (tid < NB) ? g_hist[tid] : 0;
    if (tid < NB) sd[tid] = v2;
    __syncthreads();
    for (int d = 1; d < NB; d <<= 1) {
        int add = (tid >= d && tid < NB) ? sd[tid - d] : 0;
        __syncthreads();
        if (tid < NB) sd[tid] += add;
        __syncthreads();
    }
    if (tid < NB) {
        int i2 = sd[tid];
        g_off[tid] = i2 - v2;
        g_cursor[tid] = i2 - v2;
        if (tid == NB - 1) g_off[NB] = i2;
    }
}

// ------------------------------------------------------------------
// Per-electron precompute. 16 threads per 4 electrons (best data-reuse
// config), packed f32x2 h2 accumulators along dim-pairs: W2 dim-pairs
// load straight out of the float4 smem tile as ulonglong2 (no repack).
__global__ __launch_bounds__(128) void k_pre(
                      const float* __restrict__ si, const float* __restrict__ zp,
                      const float* __restrict__ mk,
                      const float* __restrict__ W1, const float* __restrict__ b1,
                      const float* __restrict__ W2, const float* __restrict__ b2,
                      const float* __restrict__ W3, const float* __restrict__ b3,
                      const float* __restrict__ el, const float* __restrict__ sloc)
{
    __shared__ float  W1s[128], b1s[64];
    __shared__ float4 W2s4[64 * 32];
    __shared__ unsigned long long b2u[64];
    __shared__ float  W3s[128];
    __shared__ float  axs[48], ays[48];
    int tid = threadIdx.x;
    if (tid < 128) W1s[tid] = W1[tid];
    if (tid < 64)  b1s[tid] = b1[tid];
    {
        const float4* w2 = (const float4*)W2;
        for (int i = tid; i < 64 * 32; i += blockDim.x) W2s4[i] = w2[i];
    }
    if (tid < 64)  b2u[tid] = ((const unsigned long long*)b2)[tid];
    if (tid < 128) W3s[tid] = W3[tid];
    if (tid < 48)  { axs[tid] = sloc[tid * 96]; ays[tid] = sloc[tid * 2 + 1]; }
    __syncthreads();

    int lane = tid & 31;
    int o    = tid & 15;
    int grp  = tid >> 4;                      // 8 groups per CTA
    int gbase = (blockIdx.x * 8 + grp) * 4;   // 4 electrons per group
    if (gbase >= NEL) return;

    float xs[4], ys[4];
#pragma unroll
    for (int i = 0; i < 4; i++) { xs[i] = si[2 * (gbase + i)]; ys[i] = si[2 * (gbase + i) + 1]; }

    // h2 packed per electron over dim-pairs: o owns dims [8o, 8o+8) = 4 pairs
    unsigned long long h2p[4][4];
#pragma unroll
    for (int e = 0; e < 4; e++)
#pragma unroll
        for (int dp = 0; dp < 4; dp++) h2p[e][dp] = b2u[o * 4 + dp];

    const ulonglong2* W2u2 = (const ulonglong2*)W2s4;
    for (int k = 0; k < 64; k++) {
        float w1a = W1s[k], w1b = W1s[64 + k], bb = b1s[k];
        unsigned long long hp[4];
#pragma unroll
        for (int e = 0; e < 4; e++) {
            float h1 = fmaxf(fmaf(xs[e], w1a, fmaf(ys[e], w1b, bb)), 0.0f);
            hp[e] = pack2(h1);
        }
#pragma unroll
        for (int q = 0; q < 2; q++) {
            ulonglong2 w = W2u2[k * 32 + o * 2 + q];
#pragma unroll
            for (int e = 0; e < 4; e++) {
                fma2(h2p[e][2 * q],     hp[e], w.x);
                fma2(h2p[e][2 * q + 1], hp[e], w.y);
            }
        }
    }

    float rp[4] = {0.f, 0.f, 0.f, 0.f};
#pragma unroll
    for (int dp = 0; dp < 4; dp++) {
        float w3lo = W3s[o * 8 + 2 * dp];
        float w3hi = W3s[o * 8 + 2 * dp + 1];
#pragma unroll
        for (int e = 0; e < 4; e++) {
            float lo, hi;
            unpack2(h2p[e][dp], lo, hi);
            rp[e] = fmaf(fmaxf(lo, 0.f), w3lo, rp[e]);
            rp[e] = fmaf(fmaxf(hi, 0.f), w3hi, rp[e]);
        }
    }
#pragma unroll
    for (int d = 1; d < 16; d <<= 1)
#pragma unroll
        for (int e = 0; e < 4; e++)
            rp[e] += __shfl_xor_sync(0xffffffffu, rp[e], d);

    float es = el[0];
    float inv = -0.5f / (es * es);
    float cnorm = (100.0f / (es * 2.5066f)) * 0.17841241161f;

    // 4 lanes per electron: r=0 gx[0:24), r=1 gx[24:48), r=2 gy[0:24), r=3 gy[24:48)
    int myE = o >> 2;
    int r   = o & 3;
    int ei  = gbase + myE;
    float resp = rp[myE] + b3[0];
    float c = resp * mk[ei] * cnorm;
    float z = zp[ei];
    float x = xs[myE], y = ys[myE];

    int posv = 0;
    if (r == 0) {
        int b = min(max((int)z >> 2, 0), NB - 1);
        posv = atomicAdd(&g_cursor[b], 1);
    }
    int pos = __shfl_sync(0xffffffffu, posv, lane & ~3);

    if (r < 2) {
        float4* pgx = (float4*)(g_gx + (size_t)pos * 48);
#pragma unroll
        for (int q = 0; q < 6; q++) {
            int qq = r * 6 + q;
            float d0 = x - axs[4 * qq + 0], d1 = x - axs[4 * qq + 1];
            float d2 = x - axs[4 * qq + 2], d3 = x - axs[4 * qq + 3];
            pgx[qq] = make_float4(__expf(d0 * d0 * inv), __expf(d1 * d1 * inv),
                                  __expf(d2 * d2 * inv), __expf(d3 * d3 * inv));
        }
        if (r == 0) { g_z[pos] = z; g_ex[pos] = x; }
    } else {
        float4* pgy = (float4*)(g_cgy + (size_t)pos * 48);
#pragma unroll
        for (int q = 0; q < 6; q++) {
            int qq = (r - 2) * 6 + q;
            float d0 = y - ays[4 * qq + 0], d1 = y - ays[4 * qq + 1];
            float d2 = y - ays[4 * qq + 2], d3 = y - ays[4 * qq + 3];
            pgy[qq] = make_float4(c * __expf(d0 * d0 * inv), c * __expf(d1 * d1 * inv),
                                  c * __expf(d2 * d2 * inv), c * __expf(d3 * d3 * inv));
        }
    }
}

// ------------------------------------------------------------------
// Build flat per-entry records (contiguous; staging in k_main is one
// bulk copy per chunk, no per-element async ops).
__global__ void k_scatter(const float* __restrict__ el, const float* __restrict__ sloc) {
    __shared__ float sxlo[NSTRIP], sxhi[NSTRIP];
    if (threadIdx.x < NSTRIP) {
        sxlo[threadIdx.x] = sloc[(threadIdx.x * SXC) * 96];
        sxhi[threadIdx.x] = sloc[(threadIdx.x * SXC + SXC - 1) * 96];
    }
    __syncthreads();
    int pos = blockIdx.x * blockDim.x + threadIdx.x;
    if (pos >= NEL) return;
    float x = g_ex[pos], z = g_z[pos];
    int b = min(max((int)z >> 2, 0), NB - 1);
    float thr = 4.57f * el[0];

    float4 gy[12];
    const float4* gys = (const float4*)(g_cgy + (size_t)pos * 48);
#pragma unroll
    for (int j = 0; j < 12; j++) gy[j] = gys[j];
    const float* gxr = g_gx + (size_t)pos * 48;

#pragma unroll
    for (int s = 0; s < NSTRIP; s++) {
        float d = fmaxf(fmaxf(sxlo[s] - x, x - sxhi[s]), 0.0f);
        if (d < thr) {
            int q = atomicAdd(&g_scur[s * NB + b], 1);
            float4* ent = &g_ent[(size_t)q * ENTF4];
            ent[0] = make_float4(gxr[s * SXC + 0], gxr[s * SXC + 1],
                                 gxr[s * SXC + 2], gxr[s * SXC + 3]);
            ent[1] = make_float4(gxr[s * SXC + 4], gxr[s * SXC + 5], z, 0.0f);
#pragma unroll
            for (int j = 0; j < 12; j++) ent[2 + j] = gy[j];
        }
    }
}

// ------------------------------------------------------------------
// Main accumulation: CTA = (t-tile of 8 ticks, strip, split4).
// Staging = one cp.async.bulk per chunk (mbarrier completion),
// double-buffered. 144 active threads, 2 sensors each, f32x2 FMAs.
__global__ __launch_bounds__(BLK_D) void k_main(float* __restrict__ out)
{
    __shared__ float4     s_ent[2][CHUNK * ENTF4];
    __shared__ ulonglong2 s_ev2[CHUNK * 2];
    __shared__ unsigned long long s_mb[2];

    int tid = threadIdx.x;
    int t0  = blockIdx.x * TT;
    int s   = blockIdx.y;
    int sxl = tid / 24;          // 0..5 for active threads
    int q   = tid - sxl * 24;    // sensor-pair column 0..23

    unsigned mb0 = smem_u32(&s_mb[0]);
    unsigned mb1 = smem_u32(&s_mb[1]);
    unsigned dst0 = smem_u32(&s_ent[0][0]);
    unsigned dst1 = smem_u32(&s_ent[1][0]);
    if (tid == 0) { mbar_init(mb0, 1); mbar_init(mb1, 1); }
    __syncthreads();

    int blo = max(t0 - WCUT, 0) >> 2;
    int bhi = min(t0 + TT - 1 + WCUT, T_TICKS - 1) >> 2;
    int rb = g_soff[s * NB + blo], re = g_soff[s * NB + bhi + 1];
    int len = re - rb;
    int part = (len + NSPLIT - 1) / NSPLIT;
    int cb = rb + blockIdx.z * part;
    int ce = min(cb + part, re);
    int nch = (ce > cb) ? (ce - cb + CHUNK - 1) / CHUNK : 0;

    unsigned long long aa[4], ab[4];
#pragma unroll
    for (int j = 0; j < 4; j++) { aa[j] = 0ull; ab[j] = 0ull; }

    int ph0 = 0, ph1 = 0;

    // prefetch chunk 0
    if (nch > 0 && tid == 0) {
        unsigned bytes = (unsigned)min(CHUNK, ce - cb) * ENTB;
        mbar_expect_tx(mb0, bytes);
        bulk_g2s(dst0, (const char*)&g_ent[(size_t)cb * ENTF4], bytes, mb0);
    }

    for (int ch = 0; ch < nch; ch++) {
        int c0  = cb + ch * CHUNK;
        int cnt = min(CHUNK, ce - c0);
        int buf = ch & 1;

        __syncthreads();                    // compute(ch-1) done: buf^1 + s_ev2 free
        if (tid == 0 && ch + 1 < nch) {     // issue stage(ch+1) into buf^1
            int c1 = c0 + CHUNK;
            unsigned bytes = (unsigned)min(CHUNK, ce - c1) * ENTB;
            unsigned mbn = buf ? mb0 : mb1;
            unsigned dsn = buf ? dst0 : dst1;
            mbar_expect_tx(mbn, bytes);
            bulk_g2s(dsn, (const char*)&g_ent[(size_t)c1 * ENTF4], bytes, mbn);
        }
        // wait for chunk ch
        if (buf == 0) { mbar_wait(mb0, ph0); ph0 ^= 1; }
        else          { mbar_wait(mb1, ph1); ph1 ^= 1; }

        // time-gaussian weights for this 8-tick tile
        float* evf = (float*)s_ev2;
        for (int idx = tid; idx < cnt * TT; idx += BLK_D) {
            int e = idx >> 3;
            int k = idx & (TT - 1);
            float z = ((const float*)&s_ent[buf][e * ENTF4])[6];
            float d = (float)(t0 + k) - z;
            evf[idx] = __expf(-0.1f * d * d);
        }
        __syncthreads();

        if (tid < ACT_D) {
#pragma unroll 2
            for (int e = 0; e < cnt; e++) {
                const float* ep = (const float*)&s_ent[buf][e * ENTF4];
                float gxv = ep[sxl];
                float2 gy2 = *(const float2*)(ep + 8 + 2 * q);
                unsigned long long va2 = pack2(gxv * gy2.x);
                unsigned long long vb2 = pack2(gxv * gy2.y);
                ulonglong2 w0 = s_ev2[e * 2 + 0];
                ulonglong2 w1 = s_ev2[e * 2 + 1];
                fma2(aa[0], va2, w0.x); fma2(ab[0], vb2, w0.x);
                fma2(aa[1], va2, w0.y); fma2(ab[1], vb2, w0.y);
                fma2(aa[2], va2, w1.x); fma2(ab[2], vb2, w1.x);
                fma2(aa[3], va2, w1.y); fma2(ab[3], vb2, w1.y);
            }
        }
    }

    if (tid < ACT_D) {
        float fa[8], fb[8];
#pragma unroll
        for (int j = 0; j < 4; j++) {
            unpack2(aa[j], fa[2 * j], fa[2 * j + 1]);
            unpack2(ab[j], fb[2 * j], fb[2 * j + 1]);
        }
        int sx = s * SXC + sxl;
        int sy = 2 * q;
        float* dst = blockIdx.z ? (g_part + (size_t)(blockIdx.z - 1) * VOL) : out;
        float4* oa = (float4*)(dst + ((size_t)(sx * NXY + sy)) * T_TICKS + t0);
        float4* ob = (float4*)(dst + ((size_t)(sx * NXY + sy + 1)) * T_TICKS + t0);
        oa[0] = make_float4(fa[0], fa[1], fa[2], fa[3]);
        oa[1] = make_float4(fa[4], fa[5], fa[6], fa[7]);
        ob[0] = make_float4(fb[0], fb[1], fb[2], fb[3]);
        ob[1] = make_float4(fb[4], fb[5], fb[6], fb[7]);
    }
}

__global__ void k_add(float* __restrict__ out) {
    int i = blockIdx.x * blockDim.x + threadIdx.x;
    float4 a = ((const float4*)out)[i];
    float4 b0 = ((const float4*)g_part)[i];
    float4 b1 = ((const float4*)(g_part + VOL))[i];
    float4 b2 = ((const float4*)(g_part + 2 * VOL))[i];
    ((float4*)out)[i] = make_float4(a.x + b0.x + b1.x + b2.x,
                                    a.y + b0.y + b1.y + b2.y,
                                    a.z + b0.z + b1.z + b2.z,
                                    a.w + b0.w + b1.w + b2.w);
}

// ------------------------------------------------------------------
extern "C" void kernel_launch(void* const* d_in, const int* in_sizes, int n_in,
                              void* d_out, int out_size)
{
    const float* si = (const float*)d_in[0];
    const float* zp = (const float*)d_in[1];
    const float* mk = (const float*)d_in[2];
    const float* W1 = (const float*)d_in[3];
    const float* b1 = (const float*)d_in[4];
    const float* W2 = (const float*)d_in[5];
    const float* b2 = (const float*)d_in[6];
    const float* W3 = (const float*)d_in[7];
    const float* b3 = (const float*)d_in[8];
    const float* el = (const float*)d_in[9];
    const float* sl = (const float*)d_in[10];
    float* out = (float*)d_out;                // (48,48,512)

    k_zero   <<<1, NSB>>>();
    k_hist   <<<(NEL + 255) / 256, 256>>>(zp, si, el, sl);
    k_scan   <<<1, NSB>>>();
    k_pre    <<<(NEL + 31) / 32, 128>>>(si, zp, mk, W1, b1, W2, b2, W3, b3, el, sl);
    k_scatter<<<(NEL + 255) / 256, 256>>>(el, sl);
    k_main   <<<dim3(NTILE, NSTRIP, NSPLIT), BLK_D>>>(out);
    k_add    <<<(VOL / 4) / 256, 256>>>(out);
}